// round 11
// baseline (speedup 1.0000x reference)
#include <cuda_runtime.h>
#include <cuda_bf16.h>
#include <cstdint>

#define B_    64
#define T_    512
#define F_    1024
#define H_    52
#define START_ 50
#define STOP_  51

__device__ float g_emitT[(size_t)B_ * H_ * T_]; // emit transposed [b][h][t]
__device__ float g_diff[B_];

// ---------- packed fp32x2 helpers ----------
__device__ __forceinline__ unsigned long long pk2(float lo, float hi) {
    unsigned long long d;
    asm("mov.b64 %0, {%1, %2};" : "=l"(d) : "r"(__float_as_uint(lo)), "r"(__float_as_uint(hi)));
    return d;
}
__device__ __forceinline__ void upk2(unsigned long long v, float& lo, float& hi) {
    unsigned int a, b;
    asm("mov.b64 {%0, %1}, %2;" : "=r"(a), "=r"(b) : "l"(v));
    lo = __uint_as_float(a); hi = __uint_as_float(b);
}
__device__ __forceinline__ unsigned long long fma2(unsigned long long a, unsigned long long b,
                                                   unsigned long long c) {
    unsigned long long d;
    asm("fma.rn.f32x2 %0, %1, %2, %3;" : "=l"(d) : "l"(a), "l"(b), "l"(c));
    return d;
}
__device__ __forceinline__ unsigned long long add2(unsigned long long a, unsigned long long b) {
    unsigned long long d;
    asm("add.rn.f32x2 %0, %1, %2;" : "=l"(d) : "l"(a), "l"(b));
    return d;
}

// ============================================================
// Kernel 1: emit = features @ W^T + b  (M=32768, N=52, K=1024)
// Same per-thread tile as the 91.6us config (4 rows x 7 f32x2 pairs,
// 256-row block tile), but DOUBLE-BUFFERED smem with ONE
// __syncthreads per 32-k chunk (store goes to the other buffer).
// ============================================================
#define SF_ST 257
#define SF_BUFV (32 * SF_ST)
#define SW_ST 58
#define SW_BUFV (32 * SW_ST)
#define GEMM_SMEM_BYTES ((2 * SF_BUFV + 2 * SW_BUFV) * 4)   // 80640 B

__global__ void __launch_bounds__(256, 1)
emit_gemm_kernel(const float* __restrict__ feat, const float* __restrict__ W,
                 const float* __restrict__ bias) {
    extern __shared__ __align__(16) float smem[];
    float* sF = smem;                  // 2 x [32][257]
    float* sW = smem + 2 * SF_BUFV;    // 2 x [32][58]

    const int tid = threadIdx.x;
    const int cg = tid >> 6;
    const int rt = tid & 63;
    const int blockRow = blockIdx.x * 256;

    const int lrow = tid >> 3;
    const int ljj  = tid & 7;
    const int wkk  = tid & 31;
    const int whb  = tid >> 5;

    unsigned long long acc[4][7];
#pragma unroll
    for (int r = 0; r < 4; r++)
#pragma unroll
        for (int j = 0; j < 7; j++) acc[r][j] = 0ULL;

    float4 fv[8];
    float  wv[7];

    auto load_chunk = [&](int k0) {
#pragma unroll
        for (int it = 0; it < 8; it++) {
            int row = lrow + it * 32;
            fv[it] = *reinterpret_cast<const float4*>(
                &feat[(size_t)(blockRow + row) * F_ + k0 + ljj * 4]);
        }
#pragma unroll
        for (int it = 0; it < 7; it++) {
            int hh = whb + it * 8;
            wv[it] = (hh < H_) ? W[(size_t)hh * F_ + k0 + wkk] : 0.0f;
        }
    };
    auto store_chunk = [&](int buf) {
        float* f = sF + buf * SF_BUFV;
        float* w = sW + buf * SW_BUFV;
#pragma unroll
        for (int it = 0; it < 8; it++) {
            int row = lrow + it * 32;
            f[(ljj * 4 + 0) * SF_ST + row] = fv[it].x;
            f[(ljj * 4 + 1) * SF_ST + row] = fv[it].y;
            f[(ljj * 4 + 2) * SF_ST + row] = fv[it].z;
            f[(ljj * 4 + 3) * SF_ST + row] = fv[it].w;
        }
#pragma unroll
        for (int it = 0; it < 7; it++) w[wkk * SW_ST + whb + it * 8] = wv[it];
    };
    auto compute = [&](int buf) {
        const float* f = sF + buf * SF_BUFV;
        const float* w = sW + buf * SW_BUFV;
#pragma unroll 4
        for (int kk = 0; kk < 32; kk++) {
            float f0 = f[kk * SF_ST + rt];
            float f1 = f[kk * SF_ST + rt + 64];
            float f2 = f[kk * SF_ST + rt + 128];
            float f3 = f[kk * SF_ST + rt + 192];
            unsigned long long p0 = pk2(f0, f0);
            unsigned long long p1 = pk2(f1, f1);
            unsigned long long p2 = pk2(f2, f2);
            unsigned long long p3 = pk2(f3, f3);
#pragma unroll
            for (int j = 0; j < 7; j++) {
                unsigned long long w2 = *reinterpret_cast<const unsigned long long*>(
                    &w[kk * SW_ST + cg * 14 + 2 * j]);
                acc[0][j] = fma2(p0, w2, acc[0][j]);
                acc[1][j] = fma2(p1, w2, acc[1][j]);
                acc[2][j] = fma2(p2, w2, acc[2][j]);
                acc[3][j] = fma2(p3, w2, acc[3][j]);
            }
        }
    };

    // prologue: chunk0 staged into buf0, chunk1 in regs
    load_chunk(0);
    store_chunk(0);
    load_chunk(32);
    __syncthreads();

#pragma unroll 1
    for (int c = 0; c < 32; c++) {
        const int buf = c & 1;
        if (c + 1 < 32) store_chunk(buf ^ 1);      // regs hold chunk c+1; buf^1 freed by last barrier
        if (c + 2 < 32) load_chunk((c + 2) * 32);  // LDG overlaps compute
        compute(buf);
        __syncthreads();                            // chunk c done; chunk c+1 stores visible
    }

    // epilogue: + bias, store transposed
#pragma unroll
    for (int r = 0; r < 4; r++) {
        int row = blockRow + rt + r * 64;
        int b = row >> 9;
        int t = row & 511;
        size_t bbase = (size_t)b * (H_ * T_);
#pragma unroll
        for (int j = 0; j < 7; j++) {
            int col = cg * 14 + 2 * j;
            if (col + 1 < H_) {
                float lo, hi;
                upk2(acc[r][j], lo, hi);
                lo += __ldg(&bias[col]);
                hi += __ldg(&bias[col + 1]);
                g_emitT[bbase + (size_t)col * T_ + t] = lo;
                g_emitT[bbase + (size_t)(col + 1) * T_ + t] = hi;
            }
        }
    }
}

// ============================================================
// Kernel 2: CRF forward via BIDIRECTIONAL scan, 2 warps per batch
// (best-known config, unchanged from R10).
// ============================================================
__global__ void __launch_bounds__(64, 1)
crf_scan_kernel(const float* __restrict__ transition, const float* __restrict__ masks,
                const int* __restrict__ tags) {
    const int b = blockIdx.x;
    const int tid = threadIdx.x;
    const int w = tid >> 5;
    const int lane = tid & 31;
    const bool act = (lane < 26);
    const int dp = act ? lane : 0;
    const int d0 = 2 * dp, d1 = 2 * dp + 1;
    const int base = b * T_;
    const unsigned FULL = 0xFFFFFFFFu;

    __shared__ __align__(16) float bufs[2][2][104];
    __shared__ float fx[52], bx[52];
    __shared__ float offsm[2], goldsm[2], msumsm[2];

    const float* embB = &g_emitT[(size_t)b * (H_ * T_)];

    float gold = 0.0f, msum = 0.0f;
    for (int t = tid; t < T_; t += 64) {
        float mk = masks[base + t];
        int tg = tags[base + t];
        int pv = (t == 0) ? START_ : tags[base + t - 1];
        gold += mk * (embB[(size_t)tg * T_ + t] + transition[tg * H_ + pv]);
        msum += mk;
    }
#pragma unroll
    for (int s = 16; s > 0; s >>= 1) {
        gold += __shfl_xor_sync(FULL, gold, s);
        msum += __shfl_xor_sync(FULL, msum, s);
    }
    if (lane == 0) { goldsm[w] = gold; msumsm[w] = msum; }

    const float* e0 = embB + (size_t)d0 * T_;
    const float* e1 = embB + (size_t)d1 * T_;
    const float4* m4 = reinterpret_cast<const float4*>(&masks[base]);
    float (*myb)[104] = bufs[w];

    if (w == 0) {
        unsigned long long E2[52];
        {
            const float* r0 = &transition[d0 * H_];
            const float* r1 = &transition[d1 * H_];
#pragma unroll
            for (int s = 0; s < H_; s++) E2[s] = pk2(__expf(r0[s]), __expf(r1[s]));
        }
        float po0 = (d0 == START_) ? 1.0f : 0.0f;
        float po1 = 0.0f;
        if (act) *reinterpret_cast<float4*>(&myb[0][4 * dp]) = make_float4(po0, po0, po1, po1);
        float offset = 0.0f;

        float eC0[4], eC1[4];
        float4 rn0, rn1, rrn0, rrn1, mkC, mkN, mkN2;
        {
            float4 a = *reinterpret_cast<const float4*>(e0);
            float4 c = *reinterpret_cast<const float4*>(e1);
            eC0[0] = __expf(a.x); eC0[1] = __expf(a.y); eC0[2] = __expf(a.z); eC0[3] = __expf(a.w);
            eC1[0] = __expf(c.x); eC1[1] = __expf(c.y); eC1[2] = __expf(c.z); eC1[3] = __expf(c.w);
            rn0  = *reinterpret_cast<const float4*>(e0 + 4);
            rn1  = *reinterpret_cast<const float4*>(e1 + 4);
            rrn0 = *reinterpret_cast<const float4*>(e0 + 8);
            rrn1 = *reinterpret_cast<const float4*>(e1 + 8);
            mkC = m4[0]; mkN = m4[1]; mkN2 = m4[2];
        }
        __syncwarp();

        int cur = 0;
        for (int tb = 0; tb < 64; tb++) {
            float4 l0, l1, lm;
            const bool hv = (tb + 3 < 64);
            if (hv) {
                l0 = *reinterpret_cast<const float4*>(e0 + (tb + 3) * 4);
                l1 = *reinterpret_cast<const float4*>(e1 + (tb + 3) * 4);
                lm = m4[tb + 3];
            }
            float eN0[4], eN1[4];
            eN0[0] = __expf(rn0.x); eN0[1] = __expf(rn0.y); eN0[2] = __expf(rn0.z); eN0[3] = __expf(rn0.w);
            eN1[0] = __expf(rn1.x); eN1[1] = __expf(rn1.y); eN1[2] = __expf(rn1.z); eN1[3] = __expf(rn1.w);

            float rinv = 1.0f;
            if (tb) {
                float r = __shfl_sync(FULL, po0, 0);
                rinv = 1.0f / r;
                offset += __logf(r);
            }
            float mk[4] = {mkC.x, mkC.y, mkC.z, mkC.w};

#pragma unroll
            for (int s = 0; s < 4; s++) {
                const ulonglong2* u = reinterpret_cast<const ulonglong2*>(&myb[cur][0]);
                unsigned long long A0 = 0ULL, A1 = 0ULL, A2 = 0ULL, A3 = 0ULL;
#pragma unroll
                for (int q = 0; q < 26; q++) {
                    ulonglong2 uq = u[q];
                    if (q & 1) { A2 = fma2(E2[2 * q], uq.x, A2); A3 = fma2(E2[2 * q + 1], uq.y, A3); }
                    else       { A0 = fma2(E2[2 * q], uq.x, A0); A1 = fma2(E2[2 * q + 1], uq.y, A1); }
                }
                unsigned long long S2 = add2(add2(A0, A1), add2(A2, A3));
                float S0, S1;
                upk2(S2, S0, S1);
                bool on = (mk[s] > 0.5f);
                float n0 = on ? S0 * eC0[s] : po0;
                float n1 = on ? S1 * eC1[s] : po1;
                if (s == 0) { n0 *= rinv; n1 *= rinv; }
                if (act) *reinterpret_cast<float4*>(&myb[cur ^ 1][4 * dp]) = make_float4(n0, n0, n1, n1);
                po0 = n0; po1 = n1;
                cur ^= 1;
                __syncwarp();
            }

            eC0[0] = eN0[0]; eC0[1] = eN0[1]; eC0[2] = eN0[2]; eC0[3] = eN0[3];
            eC1[0] = eN1[0]; eC1[1] = eN1[1]; eC1[2] = eN1[2]; eC1[3] = eN1[3];
            rn0 = rrn0; rn1 = rrn1;
            mkC = mkN; mkN = mkN2;
            if (hv) { rrn0 = l0; rrn1 = l1; mkN2 = lm; }
        }
        if (act) { fx[d0] = po0; fx[d1] = po1; }
        if (lane == 0) offsm[0] = offset;
    } else {
        unsigned long long E2[52];
        {
#pragma unroll
            for (int dd = 0; dd < H_; dd++)
                E2[dd] = pk2(__expf(transition[dd * H_ + d0]), __expf(transition[dd * H_ + d1]));
        }
        float ro0 = __expf(transition[STOP_ * H_ + d0]);
        float ro1 = __expf(transition[STOP_ * H_ + d1]);
        float offset = 0.0f;

        float eC0[4], eC1[4];
        float4 rn0, rn1, rrn0, rrn1, mkC, mkN, mkN2;
        {
            float4 a = *reinterpret_cast<const float4*>(e0 + 127 * 4);
            float4 c = *reinterpret_cast<const float4*>(e1 + 127 * 4);
            eC0[0] = __expf(a.x); eC0[1] = __expf(a.y); eC0[2] = __expf(a.z); eC0[3] = __expf(a.w);
            eC1[0] = __expf(c.x); eC1[1] = __expf(c.y); eC1[2] = __expf(c.z); eC1[3] = __expf(c.w);
            rn0  = *reinterpret_cast<const float4*>(e0 + 126 * 4);
            rn1  = *reinterpret_cast<const float4*>(e1 + 126 * 4);
            rrn0 = *reinterpret_cast<const float4*>(e0 + 125 * 4);
            rrn1 = *reinterpret_cast<const float4*>(e1 + 125 * 4);
            mkC = m4[127]; mkN = m4[126]; mkN2 = m4[125];
        }
        __syncwarp();

        int cur = 0;
        for (int tb = 127; tb >= 64; tb--) {
            float4 l0, l1, lm;
            const bool hv = (tb - 3 >= 64);
            if (hv) {
                l0 = *reinterpret_cast<const float4*>(e0 + (tb - 3) * 4);
                l1 = *reinterpret_cast<const float4*>(e1 + (tb - 3) * 4);
                lm = m4[tb - 3];
            }
            float eN0[4], eN1[4];
            eN0[0] = __expf(rn0.x); eN0[1] = __expf(rn0.y); eN0[2] = __expf(rn0.z); eN0[3] = __expf(rn0.w);
            eN1[0] = __expf(rn1.x); eN1[1] = __expf(rn1.y); eN1[2] = __expf(rn1.z); eN1[3] = __expf(rn1.w);

            float rinv = 1.0f;
            if (tb != 127) {
                float r = __shfl_sync(FULL, ro0, 0);
                rinv = 1.0f / r;
                offset += __logf(r);
            }
            float mk[4] = {mkC.x, mkC.y, mkC.z, mkC.w};

#pragma unroll
            for (int si = 0; si < 4; si++) {
                const int s = 3 - si;
                float w0 = eC0[s] * ro0;
                float w1 = eC1[s] * ro1;
                if (act) *reinterpret_cast<float4*>(&myb[cur][4 * dp]) = make_float4(w0, w0, w1, w1);
                __syncwarp();
                const ulonglong2* u = reinterpret_cast<const ulonglong2*>(&myb[cur][0]);
                unsigned long long A0 = 0ULL, A1 = 0ULL, A2 = 0ULL, A3 = 0ULL;
#pragma unroll
                for (int q = 0; q < 26; q++) {
                    ulonglong2 uq = u[q];
                    if (q & 1) { A2 = fma2(E2[2 * q], uq.x, A2); A3 = fma2(E2[2 * q + 1], uq.y, A3); }
                    else       { A0 = fma2(E2[2 * q], uq.x, A0); A1 = fma2(E2[2 * q + 1], uq.y, A1); }
                }
                unsigned long long S2 = add2(add2(A0, A1), add2(A2, A3));
                float S0, S1;
                upk2(S2, S0, S1);
                bool on = (mk[s] > 0.5f);
                float n0 = on ? S0 : ro0;
                float n1 = on ? S1 : ro1;
                if (s == 3) { n0 *= rinv; n1 *= rinv; }
                ro0 = n0; ro1 = n1;
                cur ^= 1;
            }

            eC0[0] = eN0[0]; eC0[1] = eN0[1]; eC0[2] = eN0[2]; eC0[3] = eN0[3];
            eC1[0] = eN1[0]; eC1[1] = eN1[1]; eC1[2] = eN1[2]; eC1[3] = eN1[3];
            rn0 = rrn0; rn1 = rrn1;
            mkC = mkN; mkN = mkN2;
            if (hv) { rrn0 = l0; rrn1 = l1; mkN2 = lm; }
        }
        if (act) { bx[d0] = ro0; bx[d1] = ro1; }
        if (lane == 0) offsm[1] = offset;
    }

    __syncthreads();
    if (w == 0) {
        float term = act ? (fx[d0] * bx[d0] + fx[d1] * bx[d1]) : 0.0f;
#pragma unroll
        for (int s = 16; s > 0; s >>= 1) term += __shfl_xor_sync(FULL, term, s);
        if (lane == 0) {
            float goldT = goldsm[0] + goldsm[1];
            float msumT = msumsm[0] + msumsm[1];
            int lp = (int)(msumT + 0.5f);
            int lt = (lp > 0) ? tags[base + lp - 1] : START_;
            goldT += transition[STOP_ * H_ + lt];
            g_diff[b] = offsm[0] + offsm[1] + __logf(term) - goldT;
        }
    }
}

// ============================================================
// Kernel 3: mean over batches
// ============================================================
__global__ void __launch_bounds__(64)
finalize_kernel(float* __restrict__ out) {
    __shared__ float red[64];
    int tid = threadIdx.x;
    red[tid] = g_diff[tid];
    __syncthreads();
    for (int s = 32; s > 0; s >>= 1) { if (tid < s) red[tid] += red[tid + s]; __syncthreads(); }
    if (tid == 0) out[0] = red[0] * (1.0f / (float)B_);
}

// ============================================================
// launch
// ============================================================
extern "C" void kernel_launch(void* const* d_in, const int* in_sizes, int n_in,
                              void* d_out, int out_size) {
    const float* feat  = (const float*)d_in[0];
    const float* W     = (const float*)d_in[1];
    const float* bias  = (const float*)d_in[2];
    const float* trans = (const float*)d_in[3];
    const float* masks = (const float*)d_in[4];
    const int*   tags  = (const int*)d_in[5];
    float* out = (float*)d_out;

    cudaFuncSetAttribute(emit_gemm_kernel,
                         cudaFuncAttributeMaxDynamicSharedMemorySize, GEMM_SMEM_BYTES);

    emit_gemm_kernel<<<128, 256, GEMM_SMEM_BYTES>>>(feat, W, bias);
    crf_scan_kernel<<<B_, 64>>>(trans, masks, tags);
    finalize_kernel<<<1, 64>>>(out);
}

// round 12
// speedup vs baseline: 1.0260x; 1.0260x over previous
#include <cuda_runtime.h>
#include <cuda_bf16.h>
#include <cstdint>

#define B_    64
#define T_    512
#define F_    1024
#define H_    52
#define START_ 50
#define STOP_  51

__device__ float g_emitT[(size_t)B_ * H_ * T_]; // emit transposed [b][h][t]
__device__ float g_diff[B_];

// ---------- packed fp32x2 helpers ----------
__device__ __forceinline__ unsigned long long pk2(float lo, float hi) {
    unsigned long long d;
    asm("mov.b64 %0, {%1, %2};" : "=l"(d) : "r"(__float_as_uint(lo)), "r"(__float_as_uint(hi)));
    return d;
}
__device__ __forceinline__ void upk2(unsigned long long v, float& lo, float& hi) {
    unsigned int a, b;
    asm("mov.b64 {%0, %1}, %2;" : "=r"(a), "=r"(b) : "l"(v));
    lo = __uint_as_float(a); hi = __uint_as_float(b);
}
__device__ __forceinline__ unsigned long long fma2(unsigned long long a, unsigned long long b,
                                                   unsigned long long c) {
    unsigned long long d;
    asm("fma.rn.f32x2 %0, %1, %2, %3;" : "=l"(d) : "l"(a), "l"(b), "l"(c));
    return d;
}
__device__ __forceinline__ unsigned long long add2(unsigned long long a, unsigned long long b) {
    unsigned long long d;
    asm("add.rn.f32x2 %0, %1, %2;" : "=l"(d) : "l"(a), "l"(b));
    return d;
}

// ============================================================
// Kernel 1: emit = features @ W^T + b  (M=32768, N=52, K=1024)
// SAME per-thread tile as the 91.6us config (4 rows x 7 f32x2 pairs),
// but 128-thread CTAs with 128-row tiles and grid 256 => 2 independent
// CTAs per SM; one CTA's barrier stalls are filled by the other's math.
// Static smem, 2 syncs/chunk (known-good R5 loop structure).
// ============================================================
__global__ void __launch_bounds__(128, 2)
emit_gemm_kernel(const float* __restrict__ feat, const float* __restrict__ W,
                 const float* __restrict__ bias) {
    __shared__ float sF[32 * 129];   // [kk][row 0..127], stride 129
    __shared__ float sW[32 * 58];    // [kk][h 0..55]

    const int tid = threadIdx.x;
    const int cg = tid >> 5;        // 0..3 (column group: 14 cols each; per-warp)
    const int rt = tid & 31;        // 0..31 (row thread)
    const int blockRow = blockIdx.x * 128;

    const int lrow = tid >> 3;      // 0..15
    const int ljj  = tid & 7;       // 0..7 (float4 index within row)
    const int wkk  = tid & 31;
    const int whb  = tid >> 5;      // 0..3

    unsigned long long acc[4][7];
#pragma unroll
    for (int r = 0; r < 4; r++)
#pragma unroll
        for (int j = 0; j < 7; j++) acc[r][j] = 0ULL;

    float4 fv[8];
    float  wv[14];

    auto load_chunk = [&](int k0) {
#pragma unroll
        for (int it = 0; it < 8; it++) {
            int row = lrow + it * 16;
            fv[it] = *reinterpret_cast<const float4*>(
                &feat[(size_t)(blockRow + row) * F_ + k0 + ljj * 4]);
        }
#pragma unroll
        for (int it = 0; it < 14; it++) {
            int hh = whb + it * 4;   // 0..55
            wv[it] = (hh < H_) ? W[(size_t)hh * F_ + k0 + wkk] : 0.0f;
        }
    };
    auto store_chunk = [&]() {
#pragma unroll
        for (int it = 0; it < 8; it++) {
            int row = lrow + it * 16;
            sF[(ljj * 4 + 0) * 129 + row] = fv[it].x;
            sF[(ljj * 4 + 1) * 129 + row] = fv[it].y;
            sF[(ljj * 4 + 2) * 129 + row] = fv[it].z;
            sF[(ljj * 4 + 3) * 129 + row] = fv[it].w;
        }
#pragma unroll
        for (int it = 0; it < 14; it++) sW[wkk * 58 + whb + it * 4] = wv[it];
    };

    load_chunk(0);
    for (int k0 = 0; k0 < F_; k0 += 32) {
        __syncthreads();
        store_chunk();
        __syncthreads();
        if (k0 + 32 < F_) load_chunk(k0 + 32);

#pragma unroll 4
        for (int kk = 0; kk < 32; kk++) {
            float f0 = sF[kk * 129 + rt];
            float f1 = sF[kk * 129 + rt + 32];
            float f2 = sF[kk * 129 + rt + 64];
            float f3 = sF[kk * 129 + rt + 96];
            unsigned long long p0 = pk2(f0, f0);
            unsigned long long p1 = pk2(f1, f1);
            unsigned long long p2 = pk2(f2, f2);
            unsigned long long p3 = pk2(f3, f3);
#pragma unroll
            for (int j = 0; j < 7; j++) {
                unsigned long long w2 = *reinterpret_cast<const unsigned long long*>(
                    &sW[kk * 58 + cg * 14 + 2 * j]);
                acc[0][j] = fma2(p0, w2, acc[0][j]);
                acc[1][j] = fma2(p1, w2, acc[1][j]);
                acc[2][j] = fma2(p2, w2, acc[2][j]);
                acc[3][j] = fma2(p3, w2, acc[3][j]);
            }
        }
    }

    // epilogue: + bias, store transposed
#pragma unroll
    for (int r = 0; r < 4; r++) {
        int row = blockRow + rt + r * 32;
        int b = row >> 9;
        int t = row & 511;
        size_t bbase = (size_t)b * (H_ * T_);
#pragma unroll
        for (int j = 0; j < 7; j++) {
            int col = cg * 14 + 2 * j;
            if (col + 1 < H_) {
                float lo, hi;
                upk2(acc[r][j], lo, hi);
                lo += __ldg(&bias[col]);
                hi += __ldg(&bias[col + 1]);
                g_emitT[bbase + (size_t)col * T_ + t] = lo;
                g_emitT[bbase + (size_t)(col + 1) * T_ + t] = hi;
            }
        }
    }
}

// ============================================================
// Kernel 2: CRF forward via BIDIRECTIONAL scan, 2 warps per batch
// (best-known config, unchanged from R10: 149.5us total).
// ============================================================
__global__ void __launch_bounds__(64, 1)
crf_scan_kernel(const float* __restrict__ transition, const float* __restrict__ masks,
                const int* __restrict__ tags) {
    const int b = blockIdx.x;
    const int tid = threadIdx.x;
    const int w = tid >> 5;
    const int lane = tid & 31;
    const bool act = (lane < 26);
    const int dp = act ? lane : 0;
    const int d0 = 2 * dp, d1 = 2 * dp + 1;
    const int base = b * T_;
    const unsigned FULL = 0xFFFFFFFFu;

    __shared__ __align__(16) float bufs[2][2][104];
    __shared__ float fx[52], bx[52];
    __shared__ float offsm[2], goldsm[2], msumsm[2];

    const float* embB = &g_emitT[(size_t)b * (H_ * T_)];

    float gold = 0.0f, msum = 0.0f;
    for (int t = tid; t < T_; t += 64) {
        float mk = masks[base + t];
        int tg = tags[base + t];
        int pv = (t == 0) ? START_ : tags[base + t - 1];
        gold += mk * (embB[(size_t)tg * T_ + t] + transition[tg * H_ + pv]);
        msum += mk;
    }
#pragma unroll
    for (int s = 16; s > 0; s >>= 1) {
        gold += __shfl_xor_sync(FULL, gold, s);
        msum += __shfl_xor_sync(FULL, msum, s);
    }
    if (lane == 0) { goldsm[w] = gold; msumsm[w] = msum; }

    const float* e0 = embB + (size_t)d0 * T_;
    const float* e1 = embB + (size_t)d1 * T_;
    const float4* m4 = reinterpret_cast<const float4*>(&masks[base]);
    float (*myb)[104] = bufs[w];

    if (w == 0) {
        unsigned long long E2[52];
        {
            const float* r0 = &transition[d0 * H_];
            const float* r1 = &transition[d1 * H_];
#pragma unroll
            for (int s = 0; s < H_; s++) E2[s] = pk2(__expf(r0[s]), __expf(r1[s]));
        }
        float po0 = (d0 == START_) ? 1.0f : 0.0f;
        float po1 = 0.0f;
        if (act) *reinterpret_cast<float4*>(&myb[0][4 * dp]) = make_float4(po0, po0, po1, po1);
        float offset = 0.0f;

        float eC0[4], eC1[4];
        float4 rn0, rn1, rrn0, rrn1, mkC, mkN, mkN2;
        {
            float4 a = *reinterpret_cast<const float4*>(e0);
            float4 c = *reinterpret_cast<const float4*>(e1);
            eC0[0] = __expf(a.x); eC0[1] = __expf(a.y); eC0[2] = __expf(a.z); eC0[3] = __expf(a.w);
            eC1[0] = __expf(c.x); eC1[1] = __expf(c.y); eC1[2] = __expf(c.z); eC1[3] = __expf(c.w);
            rn0  = *reinterpret_cast<const float4*>(e0 + 4);
            rn1  = *reinterpret_cast<const float4*>(e1 + 4);
            rrn0 = *reinterpret_cast<const float4*>(e0 + 8);
            rrn1 = *reinterpret_cast<const float4*>(e1 + 8);
            mkC = m4[0]; mkN = m4[1]; mkN2 = m4[2];
        }
        __syncwarp();

        int cur = 0;
        for (int tb = 0; tb < 64; tb++) {
            float4 l0, l1, lm;
            const bool hv = (tb + 3 < 64);
            if (hv) {
                l0 = *reinterpret_cast<const float4*>(e0 + (tb + 3) * 4);
                l1 = *reinterpret_cast<const float4*>(e1 + (tb + 3) * 4);
                lm = m4[tb + 3];
            }
            float eN0[4], eN1[4];
            eN0[0] = __expf(rn0.x); eN0[1] = __expf(rn0.y); eN0[2] = __expf(rn0.z); eN0[3] = __expf(rn0.w);
            eN1[0] = __expf(rn1.x); eN1[1] = __expf(rn1.y); eN1[2] = __expf(rn1.z); eN1[3] = __expf(rn1.w);

            float rinv = 1.0f;
            if (tb) {
                float r = __shfl_sync(FULL, po0, 0);
                rinv = 1.0f / r;
                offset += __logf(r);
            }
            float mk[4] = {mkC.x, mkC.y, mkC.z, mkC.w};

#pragma unroll
            for (int s = 0; s < 4; s++) {
                const ulonglong2* u = reinterpret_cast<const ulonglong2*>(&myb[cur][0]);
                unsigned long long A0 = 0ULL, A1 = 0ULL, A2 = 0ULL, A3 = 0ULL;
#pragma unroll
                for (int q = 0; q < 26; q++) {
                    ulonglong2 uq = u[q];
                    if (q & 1) { A2 = fma2(E2[2 * q], uq.x, A2); A3 = fma2(E2[2 * q + 1], uq.y, A3); }
                    else       { A0 = fma2(E2[2 * q], uq.x, A0); A1 = fma2(E2[2 * q + 1], uq.y, A1); }
                }
                unsigned long long S2 = add2(add2(A0, A1), add2(A2, A3));
                float S0, S1;
                upk2(S2, S0, S1);
                bool on = (mk[s] > 0.5f);
                float n0 = on ? S0 * eC0[s] : po0;
                float n1 = on ? S1 * eC1[s] : po1;
                if (s == 0) { n0 *= rinv; n1 *= rinv; }
                if (act) *reinterpret_cast<float4*>(&myb[cur ^ 1][4 * dp]) = make_float4(n0, n0, n1, n1);
                po0 = n0; po1 = n1;
                cur ^= 1;
                __syncwarp();
            }

            eC0[0] = eN0[0]; eC0[1] = eN0[1]; eC0[2] = eN0[2]; eC0[3] = eN0[3];
            eC1[0] = eN1[0]; eC1[1] = eN1[1]; eC1[2] = eN1[2]; eC1[3] = eN1[3];
            rn0 = rrn0; rn1 = rrn1;
            mkC = mkN; mkN = mkN2;
            if (hv) { rrn0 = l0; rrn1 = l1; mkN2 = lm; }
        }
        if (act) { fx[d0] = po0; fx[d1] = po1; }
        if (lane == 0) offsm[0] = offset;
    } else {
        unsigned long long E2[52];
        {
#pragma unroll
            for (int dd = 0; dd < H_; dd++)
                E2[dd] = pk2(__expf(transition[dd * H_ + d0]), __expf(transition[dd * H_ + d1]));
        }
        float ro0 = __expf(transition[STOP_ * H_ + d0]);
        float ro1 = __expf(transition[STOP_ * H_ + d1]);
        float offset = 0.0f;

        float eC0[4], eC1[4];
        float4 rn0, rn1, rrn0, rrn1, mkC, mkN, mkN2;
        {
            float4 a = *reinterpret_cast<const float4*>(e0 + 127 * 4);
            float4 c = *reinterpret_cast<const float4*>(e1 + 127 * 4);
            eC0[0] = __expf(a.x); eC0[1] = __expf(a.y); eC0[2] = __expf(a.z); eC0[3] = __expf(a.w);
            eC1[0] = __expf(c.x); eC1[1] = __expf(c.y); eC1[2] = __expf(c.z); eC1[3] = __expf(c.w);
            rn0  = *reinterpret_cast<const float4*>(e0 + 126 * 4);
            rn1  = *reinterpret_cast<const float4*>(e1 + 126 * 4);
            rrn0 = *reinterpret_cast<const float4*>(e0 + 125 * 4);
            rrn1 = *reinterpret_cast<const float4*>(e1 + 125 * 4);
            mkC = m4[127]; mkN = m4[126]; mkN2 = m4[125];
        }
        __syncwarp();

        int cur = 0;
        for (int tb = 127; tb >= 64; tb--) {
            float4 l0, l1, lm;
            const bool hv = (tb - 3 >= 64);
            if (hv) {
                l0 = *reinterpret_cast<const float4*>(e0 + (tb - 3) * 4);
                l1 = *reinterpret_cast<const float4*>(e1 + (tb - 3) * 4);
                lm = m4[tb - 3];
            }
            float eN0[4], eN1[4];
            eN0[0] = __expf(rn0.x); eN0[1] = __expf(rn0.y); eN0[2] = __expf(rn0.z); eN0[3] = __expf(rn0.w);
            eN1[0] = __expf(rn1.x); eN1[1] = __expf(rn1.y); eN1[2] = __expf(rn1.z); eN1[3] = __expf(rn1.w);

            float rinv = 1.0f;
            if (tb != 127) {
                float r = __shfl_sync(FULL, ro0, 0);
                rinv = 1.0f / r;
                offset += __logf(r);
            }
            float mk[4] = {mkC.x, mkC.y, mkC.z, mkC.w};

#pragma unroll
            for (int si = 0; si < 4; si++) {
                const int s = 3 - si;
                float w0 = eC0[s] * ro0;
                float w1 = eC1[s] * ro1;
                if (act) *reinterpret_cast<float4*>(&myb[cur][4 * dp]) = make_float4(w0, w0, w1, w1);
                __syncwarp();
                const ulonglong2* u = reinterpret_cast<const ulonglong2*>(&myb[cur][0]);
                unsigned long long A0 = 0ULL, A1 = 0ULL, A2 = 0ULL, A3 = 0ULL;
#pragma unroll
                for (int q = 0; q < 26; q++) {
                    ulonglong2 uq = u[q];
                    if (q & 1) { A2 = fma2(E2[2 * q], uq.x, A2); A3 = fma2(E2[2 * q + 1], uq.y, A3); }
                    else       { A0 = fma2(E2[2 * q], uq.x, A0); A1 = fma2(E2[2 * q + 1], uq.y, A1); }
                }
                unsigned long long S2 = add2(add2(A0, A1), add2(A2, A3));
                float S0, S1;
                upk2(S2, S0, S1);
                bool on = (mk[s] > 0.5f);
                float n0 = on ? S0 : ro0;
                float n1 = on ? S1 : ro1;
                if (s == 3) { n0 *= rinv; n1 *= rinv; }
                ro0 = n0; ro1 = n1;
                cur ^= 1;
            }

            eC0[0] = eN0[0]; eC0[1] = eN0[1]; eC0[2] = eN0[2]; eC0[3] = eN0[3];
            eC1[0] = eN1[0]; eC1[1] = eN1[1]; eC1[2] = eN1[2]; eC1[3] = eN1[3];
            rn0 = rrn0; rn1 = rrn1;
            mkC = mkN; mkN = mkN2;
            if (hv) { rrn0 = l0; rrn1 = l1; mkN2 = lm; }
        }
        if (act) { bx[d0] = ro0; bx[d1] = ro1; }
        if (lane == 0) offsm[1] = offset;
    }

    __syncthreads();
    if (w == 0) {
        float term = act ? (fx[d0] * bx[d0] + fx[d1] * bx[d1]) : 0.0f;
#pragma unroll
        for (int s = 16; s > 0; s >>= 1) term += __shfl_xor_sync(FULL, term, s);
        if (lane == 0) {
            float goldT = goldsm[0] + goldsm[1];
            float msumT = msumsm[0] + msumsm[1];
            int lp = (int)(msumT + 0.5f);
            int lt = (lp > 0) ? tags[base + lp - 1] : START_;
            goldT += transition[STOP_ * H_ + lt];
            g_diff[b] = offsm[0] + offsm[1] + __logf(term) - goldT;
        }
    }
}

// ============================================================
// Kernel 3: mean over batches
// ============================================================
__global__ void __launch_bounds__(64)
finalize_kernel(float* __restrict__ out) {
    __shared__ float red[64];
    int tid = threadIdx.x;
    red[tid] = g_diff[tid];
    __syncthreads();
    for (int s = 32; s > 0; s >>= 1) { if (tid < s) red[tid] += red[tid + s]; __syncthreads(); }
    if (tid == 0) out[0] = red[0] * (1.0f / (float)B_);
}

// ============================================================
// launch
// ============================================================
extern "C" void kernel_launch(void* const* d_in, const int* in_sizes, int n_in,
                              void* d_out, int out_size) {
    const float* feat  = (const float*)d_in[0];
    const float* W     = (const float*)d_in[1];
    const float* bias  = (const float*)d_in[2];
    const float* trans = (const float*)d_in[3];
    const float* masks = (const float*)d_in[4];
    const int*   tags  = (const int*)d_in[5];
    float* out = (float*)d_out;

    emit_gemm_kernel<<<256, 128>>>(feat, W, bias);
    crf_scan_kernel<<<B_, 64>>>(trans, masks, tags);
    finalize_kernel<<<1, 64>>>(out);
}

// round 13
// speedup vs baseline: 1.0420x; 1.0156x over previous
#include <cuda_runtime.h>
#include <cuda_bf16.h>
#include <cstdint>

#define B_    64
#define T_    512
#define F_    1024
#define H_    52
#define START_ 50
#define STOP_  51

__device__ float g_emitT[(size_t)B_ * H_ * T_]; // emit transposed [b][h][t]
__device__ float g_diff[B_];

// ---------- packed fp32x2 helpers ----------
__device__ __forceinline__ unsigned long long pk2(float lo, float hi) {
    unsigned long long d;
    asm("mov.b64 %0, {%1, %2};" : "=l"(d) : "r"(__float_as_uint(lo)), "r"(__float_as_uint(hi)));
    return d;
}
__device__ __forceinline__ void upk2(unsigned long long v, float& lo, float& hi) {
    unsigned int a, b;
    asm("mov.b64 {%0, %1}, %2;" : "=r"(a), "=r"(b) : "l"(v));
    lo = __uint_as_float(a); hi = __uint_as_float(b);
}
__device__ __forceinline__ unsigned long long fma2(unsigned long long a, unsigned long long b,
                                                   unsigned long long c) {
    unsigned long long d;
    asm("fma.rn.f32x2 %0, %1, %2, %3;" : "=l"(d) : "l"(a), "l"(b), "l"(c));
    return d;
}
__device__ __forceinline__ unsigned long long add2(unsigned long long a, unsigned long long b) {
    unsigned long long d;
    asm("add.rn.f32x2 %0, %1, %2;" : "=l"(d) : "l"(a), "l"(b));
    return d;
}

// ============================================================
// Kernel 1: emit GEMM — FROZEN best-measured config (91.4us, R5).
// 128 blocks x 256 threads, 256-row tile, 4 rows x 7 pairs/thread,
// static smem, 2 syncs/chunk. Output transposed g_emitT[b][h][t].
// ============================================================
__global__ void __launch_bounds__(256, 1)
emit_gemm_kernel(const float* __restrict__ feat, const float* __restrict__ W,
                 const float* __restrict__ bias) {
    __shared__ float sF[32 * 257];
    __shared__ float sW[32 * 58];

    const int tid = threadIdx.x;
    const int cg = tid >> 6;
    const int rt = tid & 63;
    const int blockRow = blockIdx.x * 256;

    const int lrow = tid >> 3;
    const int ljj  = tid & 7;
    const int wkk  = tid & 31;
    const int whb  = tid >> 5;

    unsigned long long acc[4][7];
#pragma unroll
    for (int r = 0; r < 4; r++)
#pragma unroll
        for (int j = 0; j < 7; j++) acc[r][j] = 0ULL;

    float4 fv[8];
    float  wv[7];

    auto load_chunk = [&](int k0) {
#pragma unroll
        for (int it = 0; it < 8; it++) {
            int row = lrow + it * 32;
            fv[it] = *reinterpret_cast<const float4*>(
                &feat[(size_t)(blockRow + row) * F_ + k0 + ljj * 4]);
        }
#pragma unroll
        for (int it = 0; it < 7; it++) {
            int hh = whb + it * 8;
            wv[it] = (hh < H_) ? W[(size_t)hh * F_ + k0 + wkk] : 0.0f;
        }
    };
    auto store_chunk = [&]() {
#pragma unroll
        for (int it = 0; it < 8; it++) {
            int row = lrow + it * 32;
            sF[(ljj * 4 + 0) * 257 + row] = fv[it].x;
            sF[(ljj * 4 + 1) * 257 + row] = fv[it].y;
            sF[(ljj * 4 + 2) * 257 + row] = fv[it].z;
            sF[(ljj * 4 + 3) * 257 + row] = fv[it].w;
        }
#pragma unroll
        for (int it = 0; it < 7; it++) sW[wkk * 58 + whb + it * 8] = wv[it];
    };

    load_chunk(0);
    for (int k0 = 0; k0 < F_; k0 += 32) {
        __syncthreads();
        store_chunk();
        __syncthreads();
        if (k0 + 32 < F_) load_chunk(k0 + 32);

#pragma unroll 4
        for (int kk = 0; kk < 32; kk++) {
            float f0 = sF[kk * 257 + rt];
            float f1 = sF[kk * 257 + rt + 64];
            float f2 = sF[kk * 257 + rt + 128];
            float f3 = sF[kk * 257 + rt + 192];
            unsigned long long p0 = pk2(f0, f0);
            unsigned long long p1 = pk2(f1, f1);
            unsigned long long p2 = pk2(f2, f2);
            unsigned long long p3 = pk2(f3, f3);
#pragma unroll
            for (int j = 0; j < 7; j++) {
                unsigned long long w2 = *reinterpret_cast<const unsigned long long*>(
                    &sW[kk * 58 + cg * 14 + 2 * j]);
                acc[0][j] = fma2(p0, w2, acc[0][j]);
                acc[1][j] = fma2(p1, w2, acc[1][j]);
                acc[2][j] = fma2(p2, w2, acc[2][j]);
                acc[3][j] = fma2(p3, w2, acc[3][j]);
            }
        }
    }

#pragma unroll
    for (int r = 0; r < 4; r++) {
        int row = blockRow + rt + r * 64;
        int b = row >> 9;
        int t = row & 511;
        size_t bbase = (size_t)b * (H_ * T_);
#pragma unroll
        for (int j = 0; j < 7; j++) {
            int col = cg * 14 + 2 * j;
            if (col + 1 < H_) {
                float lo, hi;
                upk2(acc[r][j], lo, hi);
                lo += __ldg(&bias[col]);
                hi += __ldg(&bias[col + 1]);
                g_emitT[bbase + (size_t)col * T_ + t] = lo;
                g_emitT[bbase + (size_t)(col + 1) * T_ + t] = hi;
            }
        }
    }
}

// ============================================================
// Kernel 2: CRF forward via BIDIRECTIONAL scan, 2 warps per batch.
// DE-DIVERGED hot loop: exchange buffers padded to 32 dest pairs so
// ALL 32 lanes store unconditionally every step (lanes 26..31 write
// padding, read clamped-valid rows, results never consumed).
// No branches inside the step loop => no BSSY/BSYNC per step.
// ============================================================
__global__ void __launch_bounds__(64, 1)
crf_scan_kernel(const float* __restrict__ transition, const float* __restrict__ masks,
                const int* __restrict__ tags) {
    const int b = blockIdx.x;
    const int tid = threadIdx.x;
    const int w = tid >> 5;
    const int lane = tid & 31;
    const bool act = (lane < 26);
    const int d0 = 2 * lane;             // 0..62 (may exceed 51 for pad lanes)
    const int d1 = 2 * lane + 1;
    const int c0 = (d0 < H_) ? d0 : 0;   // clamped for memory safety
    const int c1 = (d1 < H_) ? d1 : 0;
    const int base = b * T_;
    const unsigned FULL = 0xFFFFFFFFu;

    __shared__ __align__(16) float bufs[2][2][128];   // [warp][parity][32 pairs x 4]
    __shared__ float fx[52], bx[52];
    __shared__ float offsm[2], goldsm[2], msumsm[2];

    const float* embB = &g_emitT[(size_t)b * (H_ * T_)];

    // ---- gold partials ----
    float gold = 0.0f, msum = 0.0f;
    for (int t = tid; t < T_; t += 64) {
        float mk = masks[base + t];
        int tg = tags[base + t];
        int pv = (t == 0) ? START_ : tags[base + t - 1];
        gold += mk * (embB[(size_t)tg * T_ + t] + transition[tg * H_ + pv]);
        msum += mk;
    }
#pragma unroll
    for (int s = 16; s > 0; s >>= 1) {
        gold += __shfl_xor_sync(FULL, gold, s);
        msum += __shfl_xor_sync(FULL, msum, s);
    }
    if (lane == 0) { goldsm[w] = gold; msumsm[w] = msum; }

    const float* e0 = embB + (size_t)c0 * T_;
    const float* e1 = embB + (size_t)c1 * T_;
    const float4* m4 = reinterpret_cast<const float4*>(&masks[base]);
    float (*myb)[128] = bufs[w];

    if (w == 0) {
        // ================= FORWARD: t = 0..255 =================
        unsigned long long E2[52];
        {
            const float* r0 = &transition[c0 * H_];
            const float* r1 = &transition[c1 * H_];
#pragma unroll
            for (int s = 0; s < H_; s++) E2[s] = pk2(__expf(r0[s]), __expf(r1[s]));
        }
        float po0 = (d0 == START_) ? 1.0f : 0.0f;
        float po1 = 0.0f;
        *reinterpret_cast<float4*>(&myb[0][4 * lane]) = make_float4(po0, po0, po1, po1);
        float offset = 0.0f;

        float eC0[4], eC1[4];
        float4 rn0, rn1, rrn0, rrn1, mkC, mkN, mkN2;
        {
            float4 a = *reinterpret_cast<const float4*>(e0);
            float4 c = *reinterpret_cast<const float4*>(e1);
            eC0[0] = __expf(a.x); eC0[1] = __expf(a.y); eC0[2] = __expf(a.z); eC0[3] = __expf(a.w);
            eC1[0] = __expf(c.x); eC1[1] = __expf(c.y); eC1[2] = __expf(c.z); eC1[3] = __expf(c.w);
            rn0  = *reinterpret_cast<const float4*>(e0 + 4);
            rn1  = *reinterpret_cast<const float4*>(e1 + 4);
            rrn0 = *reinterpret_cast<const float4*>(e0 + 8);
            rrn1 = *reinterpret_cast<const float4*>(e1 + 8);
            mkC = m4[0]; mkN = m4[1]; mkN2 = m4[2];
        }
        __syncwarp();

        int cur = 0;
        for (int tb = 0; tb < 64; tb++) {
            float4 l0, l1, lm;
            const bool hv = (tb + 3 < 64);
            if (hv) {
                l0 = *reinterpret_cast<const float4*>(e0 + (tb + 3) * 4);
                l1 = *reinterpret_cast<const float4*>(e1 + (tb + 3) * 4);
                lm = m4[tb + 3];
            }
            float eN0[4], eN1[4];
            eN0[0] = __expf(rn0.x); eN0[1] = __expf(rn0.y); eN0[2] = __expf(rn0.z); eN0[3] = __expf(rn0.w);
            eN1[0] = __expf(rn1.x); eN1[1] = __expf(rn1.y); eN1[2] = __expf(rn1.z); eN1[3] = __expf(rn1.w);

            float rinv = 1.0f;
            if (tb) {
                float r = __shfl_sync(FULL, po0, 0);
                rinv = 1.0f / r;
                offset += __logf(r);
            }
            float mk[4] = {mkC.x, mkC.y, mkC.z, mkC.w};

#pragma unroll
            for (int s = 0; s < 4; s++) {
                const ulonglong2* u = reinterpret_cast<const ulonglong2*>(&myb[cur][0]);
                unsigned long long A0 = 0ULL, A1 = 0ULL, A2 = 0ULL, A3 = 0ULL;
#pragma unroll
                for (int q = 0; q < 26; q++) {
                    ulonglong2 uq = u[q];
                    if (q & 1) { A2 = fma2(E2[2 * q], uq.x, A2); A3 = fma2(E2[2 * q + 1], uq.y, A3); }
                    else       { A0 = fma2(E2[2 * q], uq.x, A0); A1 = fma2(E2[2 * q + 1], uq.y, A1); }
                }
                unsigned long long S2 = add2(add2(A0, A1), add2(A2, A3));
                float S0, S1;
                upk2(S2, S0, S1);
                bool on = (mk[s] > 0.5f);
                float n0 = on ? S0 * eC0[s] : po0;
                float n1 = on ? S1 * eC1[s] : po1;
                if (s == 0) { n0 *= rinv; n1 *= rinv; }
                *reinterpret_cast<float4*>(&myb[cur ^ 1][4 * lane]) = make_float4(n0, n0, n1, n1);
                po0 = n0; po1 = n1;
                cur ^= 1;
                __syncwarp();
            }

            eC0[0] = eN0[0]; eC0[1] = eN0[1]; eC0[2] = eN0[2]; eC0[3] = eN0[3];
            eC1[0] = eN1[0]; eC1[1] = eN1[1]; eC1[2] = eN1[2]; eC1[3] = eN1[3];
            rn0 = rrn0; rn1 = rrn1;
            mkC = mkN; mkN = mkN2;
            if (hv) { rrn0 = l0; rrn1 = l1; mkN2 = lm; }
        }
        if (act) { fx[d0] = po0; fx[d1] = po1; }
        if (lane == 0) offsm[0] = offset;
    } else {
        // ================= BACKWARD: t = 511..256 =================
        unsigned long long E2[52];
        {
#pragma unroll
            for (int dd = 0; dd < H_; dd++)
                E2[dd] = pk2(__expf(transition[dd * H_ + c0]), __expf(transition[dd * H_ + c1]));
        }
        float ro0 = __expf(transition[STOP_ * H_ + c0]);
        float ro1 = __expf(transition[STOP_ * H_ + c1]);
        float offset = 0.0f;

        float eC0[4], eC1[4];
        float4 rn0, rn1, rrn0, rrn1, mkC, mkN, mkN2;
        {
            float4 a = *reinterpret_cast<const float4*>(e0 + 127 * 4);
            float4 c = *reinterpret_cast<const float4*>(e1 + 127 * 4);
            eC0[0] = __expf(a.x); eC0[1] = __expf(a.y); eC0[2] = __expf(a.z); eC0[3] = __expf(a.w);
            eC1[0] = __expf(c.x); eC1[1] = __expf(c.y); eC1[2] = __expf(c.z); eC1[3] = __expf(c.w);
            rn0  = *reinterpret_cast<const float4*>(e0 + 126 * 4);
            rn1  = *reinterpret_cast<const float4*>(e1 + 126 * 4);
            rrn0 = *reinterpret_cast<const float4*>(e0 + 125 * 4);
            rrn1 = *reinterpret_cast<const float4*>(e1 + 125 * 4);
            mkC = m4[127]; mkN = m4[126]; mkN2 = m4[125];
        }
        __syncwarp();

        int cur = 0;
        for (int tb = 127; tb >= 64; tb--) {
            float4 l0, l1, lm;
            const bool hv = (tb - 3 >= 64);
            if (hv) {
                l0 = *reinterpret_cast<const float4*>(e0 + (tb - 3) * 4);
                l1 = *reinterpret_cast<const float4*>(e1 + (tb - 3) * 4);
                lm = m4[tb - 3];
            }
            float eN0[4], eN1[4];
            eN0[0] = __expf(rn0.x); eN0[1] = __expf(rn0.y); eN0[2] = __expf(rn0.z); eN0[3] = __expf(rn0.w);
            eN1[0] = __expf(rn1.x); eN1[1] = __expf(rn1.y); eN1[2] = __expf(rn1.z); eN1[3] = __expf(rn1.w);

            float rinv = 1.0f;
            if (tb != 127) {
                float r = __shfl_sync(FULL, ro0, 0);
                rinv = 1.0f / r;
                offset += __logf(r);
            }
            float mk[4] = {mkC.x, mkC.y, mkC.z, mkC.w};

#pragma unroll
            for (int si = 0; si < 4; si++) {
                const int s = 3 - si;
                float w0 = eC0[s] * ro0;
                float w1 = eC1[s] * ro1;
                *reinterpret_cast<float4*>(&myb[cur][4 * lane]) = make_float4(w0, w0, w1, w1);
                __syncwarp();
                const ulonglong2* u = reinterpret_cast<const ulonglong2*>(&myb[cur][0]);
                unsigned long long A0 = 0ULL, A1 = 0ULL, A2 = 0ULL, A3 = 0ULL;
#pragma unroll
                for (int q = 0; q < 26; q++) {
                    ulonglong2 uq = u[q];
                    if (q & 1) { A2 = fma2(E2[2 * q], uq.x, A2); A3 = fma2(E2[2 * q + 1], uq.y, A3); }
                    else       { A0 = fma2(E2[2 * q], uq.x, A0); A1 = fma2(E2[2 * q + 1], uq.y, A1); }
                }
                unsigned long long S2 = add2(add2(A0, A1), add2(A2, A3));
                float S0, S1;
                upk2(S2, S0, S1);
                bool on = (mk[s] > 0.5f);
                float n0 = on ? S0 : ro0;
                float n1 = on ? S1 : ro1;
                if (s == 3) { n0 *= rinv; n1 *= rinv; }
                ro0 = n0; ro1 = n1;
                cur ^= 1;
            }

            eC0[0] = eN0[0]; eC0[1] = eN0[1]; eC0[2] = eN0[2]; eC0[3] = eN0[3];
            eC1[0] = eN1[0]; eC1[1] = eN1[1]; eC1[2] = eN1[2]; eC1[3] = eN1[3];
            rn0 = rrn0; rn1 = rrn1;
            mkC = mkN; mkN = mkN2;
            if (hv) { rrn0 = l0; rrn1 = l1; mkN2 = lm; }
        }
        if (act) { bx[d0] = ro0; bx[d1] = ro1; }
        if (lane == 0) offsm[1] = offset;
    }

    __syncthreads();
    if (w == 0) {
        float term = act ? (fx[d0] * bx[d0] + fx[d1] * bx[d1]) : 0.0f;
#pragma unroll
        for (int s = 16; s > 0; s >>= 1) term += __shfl_xor_sync(FULL, term, s);
        if (lane == 0) {
            float goldT = goldsm[0] + goldsm[1];
            float msumT = msumsm[0] + msumsm[1];
            int lp = (int)(msumT + 0.5f);
            int lt = (lp > 0) ? tags[base + lp - 1] : START_;
            goldT += transition[STOP_ * H_ + lt];
            g_diff[b] = offsm[0] + offsm[1] + __logf(term) - goldT;
        }
    }
}

// ============================================================
// Kernel 3: mean over batches
// ============================================================
__global__ void __launch_bounds__(64)
finalize_kernel(float* __restrict__ out) {
    __shared__ float red[64];
    int tid = threadIdx.x;
    red[tid] = g_diff[tid];
    __syncthreads();
    for (int s = 32; s > 0; s >>= 1) { if (tid < s) red[tid] += red[tid + s]; __syncthreads(); }
    if (tid == 0) out[0] = red[0] * (1.0f / (float)B_);
}

// ============================================================
// launch
// ============================================================
extern "C" void kernel_launch(void* const* d_in, const int* in_sizes, int n_in,
                              void* d_out, int out_size) {
    const float* feat  = (const float*)d_in[0];
    const float* W     = (const float*)d_in[1];
    const float* bias  = (const float*)d_in[2];
    const float* trans = (const float*)d_in[3];
    const float* masks = (const float*)d_in[4];
    const int*   tags  = (const int*)d_in[5];
    float* out = (float*)d_out;

    emit_gemm_kernel<<<128, 256>>>(feat, W, bias);
    crf_scan_kernel<<<B_, 64>>>(trans, masks, tags);
    finalize_kernel<<<1, 64>>>(out);
}

// round 14
// speedup vs baseline: 1.1104x; 1.0657x over previous
#include <cuda_runtime.h>
#include <cuda_bf16.h>
#include <cstdint>

#define B_    64
#define T_    512
#define F_    1024
#define H_    52
#define START_ 50
#define STOP_  51

__device__ float g_emitT[(size_t)B_ * H_ * T_]; // emit transposed [b][h][t]
__device__ float g_diff[B_];

// ---------- packed fp32x2 helpers (scan) ----------
__device__ __forceinline__ unsigned long long pk2(float lo, float hi) {
    unsigned long long d;
    asm("mov.b64 %0, {%1, %2};" : "=l"(d) : "r"(__float_as_uint(lo)), "r"(__float_as_uint(hi)));
    return d;
}
__device__ __forceinline__ void upk2(unsigned long long v, float& lo, float& hi) {
    unsigned int a, b;
    asm("mov.b64 {%0, %1}, %2;" : "=r"(a), "=r"(b) : "l"(v));
    lo = __uint_as_float(a); hi = __uint_as_float(b);
}
__device__ __forceinline__ unsigned long long fma2(unsigned long long a, unsigned long long b,
                                                   unsigned long long c) {
    unsigned long long d;
    asm("fma.rn.f32x2 %0, %1, %2, %3;" : "=l"(d) : "l"(a), "l"(b), "l"(c));
    return d;
}
__device__ __forceinline__ unsigned long long add2(unsigned long long a, unsigned long long b) {
    unsigned long long d;
    asm("add.rn.f32x2 %0, %1, %2;" : "=l"(d) : "l"(a), "l"(b));
    return d;
}

// ---------- tf32 mma (Ampere-class, valid on sm_103) ----------
__device__ __forceinline__ void mma_tf32(float* d, const uint32_t* a, uint32_t b0, uint32_t b1) {
    asm volatile(
        "mma.sync.aligned.m16n8k8.row.col.f32.tf32.tf32.f32 "
        "{%0,%1,%2,%3}, {%4,%5,%6,%7}, {%8,%9}, {%0,%1,%2,%3};"
        : "+f"(d[0]), "+f"(d[1]), "+f"(d[2]), "+f"(d[3])
        : "r"(a[0]), "r"(a[1]), "r"(a[2]), "r"(a[3]), "r"(b0), "r"(b1));
}

// ============================================================
// Kernel 1: emit = features @ W^T + b via tf32 mma.sync.
// 128 blocks x 256 threads (8 warps). Block tile 256 rows x 56 cols.
// Warp w owns rows [32w, 32w+32): 2 m16 tiles x 7 n8 tiles.
// K staged in 32-chunks (winning skeleton), fragments from smem.
// Output transposed g_emitT[b][h][t] via smem staging (2 passes).
// ============================================================
#define SA_ST 264   // 264 % 32 == 8 -> frag loads conflict-free
#define SB_ST 73    // 73  % 32 == 9 -> stores conflict-free, frag loads <=2-way

__global__ void __launch_bounds__(256, 2)
emit_gemm_kernel(const float* __restrict__ feat, const float* __restrict__ W,
                 const float* __restrict__ bias) {
    __shared__ float sA[32 * SA_ST];   // [k 0..31][row 0..255 (+pad)]  33.8KB
    __shared__ float sB[32 * SB_ST];   // [k 0..31][n 0..55 (+pad)]      9.3KB

    const int tid = threadIdx.x;
    const int lane = tid & 31;
    const int w = tid >> 5;            // warp 0..7
    const int a_ = lane >> 2;          // group id 0..7
    const int b_ = lane & 3;           // thread-in-group 0..3
    const int blockRow = blockIdx.x * 256;

    float c[2][7][4];
#pragma unroll
    for (int mt = 0; mt < 2; mt++)
#pragma unroll
        for (int nt = 0; nt < 7; nt++)
#pragma unroll
            for (int j = 0; j < 4; j++) c[mt][nt][j] = 0.0f;

    float4 fv[8];
    float  wv[7];

    auto load_chunk = [&](int k0) {
#pragma unroll
        for (int it = 0; it < 8; it++) {
            int row = lane + it * 32;
            fv[it] = *reinterpret_cast<const float4*>(
                &feat[(size_t)(blockRow + row) * F_ + k0 + w * 4]);
        }
#pragma unroll
        for (int it = 0; it < 7; it++) {
            int hh = w + it * 8;       // 0..55
            wv[it] = (hh < H_) ? W[(size_t)hh * F_ + k0 + lane] : 0.0f;
        }
    };
    auto store_chunk = [&]() {
#pragma unroll
        for (int it = 0; it < 8; it++) {
            int row = lane + it * 32;
            sA[(w * 4 + 0) * SA_ST + row] = fv[it].x;
            sA[(w * 4 + 1) * SA_ST + row] = fv[it].y;
            sA[(w * 4 + 2) * SA_ST + row] = fv[it].z;
            sA[(w * 4 + 3) * SA_ST + row] = fv[it].w;
        }
#pragma unroll
        for (int it = 0; it < 7; it++) sB[lane * SB_ST + w + it * 8] = wv[it];
    };
    auto compute = [&]() {
        const int rb = w * 32;
#pragma unroll
        for (int ks = 0; ks < 4; ks++) {
            const int kb = ks * 8;
            uint32_t A0[4], A1[4];
            A0[0] = __float_as_uint(sA[(kb + b_) * SA_ST + rb + a_]);
            A0[1] = __float_as_uint(sA[(kb + b_) * SA_ST + rb + a_ + 8]);
            A0[2] = __float_as_uint(sA[(kb + b_ + 4) * SA_ST + rb + a_]);
            A0[3] = __float_as_uint(sA[(kb + b_ + 4) * SA_ST + rb + a_ + 8]);
            A1[0] = __float_as_uint(sA[(kb + b_) * SA_ST + rb + 16 + a_]);
            A1[1] = __float_as_uint(sA[(kb + b_) * SA_ST + rb + 16 + a_ + 8]);
            A1[2] = __float_as_uint(sA[(kb + b_ + 4) * SA_ST + rb + 16 + a_]);
            A1[3] = __float_as_uint(sA[(kb + b_ + 4) * SA_ST + rb + 16 + a_ + 8]);
#pragma unroll
            for (int nt = 0; nt < 7; nt++) {
                uint32_t B0 = __float_as_uint(sB[(kb + b_) * SB_ST + nt * 8 + a_]);
                uint32_t B1 = __float_as_uint(sB[(kb + b_ + 4) * SB_ST + nt * 8 + a_]);
                mma_tf32(c[0][nt], A0, B0, B1);
                mma_tf32(c[1][nt], A1, B0, B1);
            }
        }
    };

    load_chunk(0);
    for (int k0 = 0; k0 < F_; k0 += 32) {
        __syncthreads();
        store_chunk();
        __syncthreads();
        if (k0 + 32 < F_) load_chunk(k0 + 32);
        compute();
    }

    // ---- epilogue: stage [col][row] in smem, coalesced transposed store ----
    const int bIdx = blockRow >> 9;
    const int t0 = blockRow & 511;
    const size_t bbase = (size_t)bIdx * (H_ * T_);
    float* stage = sA;                 // 28*258 = 7224 <= 8448 floats

    __syncthreads();                   // main loop smem reads done
#pragma unroll 1
    for (int pass = 0; pass < 2; pass++) {
        const int cb = pass * 28;
#pragma unroll
        for (int mt = 0; mt < 2; mt++)
#pragma unroll
            for (int nt = 0; nt < 7; nt++)
#pragma unroll
                for (int j = 0; j < 4; j++) {
                    int col = nt * 8 + 2 * b_ + (j & 1);
                    int row = w * 32 + mt * 16 + a_ + ((j >> 1) * 8);
                    if (col >= cb && col < cb + 28)
                        stage[(col - cb) * 258 + row] = c[mt][nt][j];
                }
        __syncthreads();
        for (int e = tid; e < 28 * 256; e += 256) {
            int cc = e >> 8, r = e & 255;
            int colg = cb + cc;
            if (colg < H_)
                g_emitT[bbase + (size_t)colg * T_ + t0 + r] =
                    stage[cc * 258 + r] + __ldg(&bias[colg]);
        }
        __syncthreads();
    }
}

// ============================================================
// Kernel 2: CRF forward via BIDIRECTIONAL scan (R13 best config,
// de-diverged hot loop, unchanged).
// ============================================================
__global__ void __launch_bounds__(64, 1)
crf_scan_kernel(const float* __restrict__ transition, const float* __restrict__ masks,
                const int* __restrict__ tags) {
    const int b = blockIdx.x;
    const int tid = threadIdx.x;
    const int w = tid >> 5;
    const int lane = tid & 31;
    const bool act = (lane < 26);
    const int d0 = 2 * lane;
    const int d1 = 2 * lane + 1;
    const int c0 = (d0 < H_) ? d0 : 0;
    const int c1 = (d1 < H_) ? d1 : 0;
    const int base = b * T_;
    const unsigned FULL = 0xFFFFFFFFu;

    __shared__ __align__(16) float bufs[2][2][128];
    __shared__ float fx[52], bx[52];
    __shared__ float offsm[2], goldsm[2], msumsm[2];

    const float* embB = &g_emitT[(size_t)b * (H_ * T_)];

    float gold = 0.0f, msum = 0.0f;
    for (int t = tid; t < T_; t += 64) {
        float mk = masks[base + t];
        int tg = tags[base + t];
        int pv = (t == 0) ? START_ : tags[base + t - 1];
        gold += mk * (embB[(size_t)tg * T_ + t] + transition[tg * H_ + pv]);
        msum += mk;
    }
#pragma unroll
    for (int s = 16; s > 0; s >>= 1) {
        gold += __shfl_xor_sync(FULL, gold, s);
        msum += __shfl_xor_sync(FULL, msum, s);
    }
    if (lane == 0) { goldsm[w] = gold; msumsm[w] = msum; }

    const float* e0 = embB + (size_t)c0 * T_;
    const float* e1 = embB + (size_t)c1 * T_;
    const float4* m4 = reinterpret_cast<const float4*>(&masks[base]);
    float (*myb)[128] = bufs[w];

    if (w == 0) {
        unsigned long long E2[52];
        {
            const float* r0 = &transition[c0 * H_];
            const float* r1 = &transition[c1 * H_];
#pragma unroll
            for (int s = 0; s < H_; s++) E2[s] = pk2(__expf(r0[s]), __expf(r1[s]));
        }
        float po0 = (d0 == START_) ? 1.0f : 0.0f;
        float po1 = 0.0f;
        *reinterpret_cast<float4*>(&myb[0][4 * lane]) = make_float4(po0, po0, po1, po1);
        float offset = 0.0f;

        float eC0[4], eC1[4];
        float4 rn0, rn1, rrn0, rrn1, mkC, mkN, mkN2;
        {
            float4 a = *reinterpret_cast<const float4*>(e0);
            float4 c = *reinterpret_cast<const float4*>(e1);
            eC0[0] = __expf(a.x); eC0[1] = __expf(a.y); eC0[2] = __expf(a.z); eC0[3] = __expf(a.w);
            eC1[0] = __expf(c.x); eC1[1] = __expf(c.y); eC1[2] = __expf(c.z); eC1[3] = __expf(c.w);
            rn0  = *reinterpret_cast<const float4*>(e0 + 4);
            rn1  = *reinterpret_cast<const float4*>(e1 + 4);
            rrn0 = *reinterpret_cast<const float4*>(e0 + 8);
            rrn1 = *reinterpret_cast<const float4*>(e1 + 8);
            mkC = m4[0]; mkN = m4[1]; mkN2 = m4[2];
        }
        __syncwarp();

        int cur = 0;
        for (int tb = 0; tb < 64; tb++) {
            float4 l0, l1, lm;
            const bool hv = (tb + 3 < 64);
            if (hv) {
                l0 = *reinterpret_cast<const float4*>(e0 + (tb + 3) * 4);
                l1 = *reinterpret_cast<const float4*>(e1 + (tb + 3) * 4);
                lm = m4[tb + 3];
            }
            float eN0[4], eN1[4];
            eN0[0] = __expf(rn0.x); eN0[1] = __expf(rn0.y); eN0[2] = __expf(rn0.z); eN0[3] = __expf(rn0.w);
            eN1[0] = __expf(rn1.x); eN1[1] = __expf(rn1.y); eN1[2] = __expf(rn1.z); eN1[3] = __expf(rn1.w);

            float rinv = 1.0f;
            if (tb) {
                float r = __shfl_sync(FULL, po0, 0);
                rinv = 1.0f / r;
                offset += __logf(r);
            }
            float mk[4] = {mkC.x, mkC.y, mkC.z, mkC.w};

#pragma unroll
            for (int s = 0; s < 4; s++) {
                const ulonglong2* u = reinterpret_cast<const ulonglong2*>(&myb[cur][0]);
                unsigned long long A0 = 0ULL, A1 = 0ULL, A2 = 0ULL, A3 = 0ULL;
#pragma unroll
                for (int q = 0; q < 26; q++) {
                    ulonglong2 uq = u[q];
                    if (q & 1) { A2 = fma2(E2[2 * q], uq.x, A2); A3 = fma2(E2[2 * q + 1], uq.y, A3); }
                    else       { A0 = fma2(E2[2 * q], uq.x, A0); A1 = fma2(E2[2 * q + 1], uq.y, A1); }
                }
                unsigned long long S2 = add2(add2(A0, A1), add2(A2, A3));
                float S0, S1;
                upk2(S2, S0, S1);
                bool on = (mk[s] > 0.5f);
                float n0 = on ? S0 * eC0[s] : po0;
                float n1 = on ? S1 * eC1[s] : po1;
                if (s == 0) { n0 *= rinv; n1 *= rinv; }
                *reinterpret_cast<float4*>(&myb[cur ^ 1][4 * lane]) = make_float4(n0, n0, n1, n1);
                po0 = n0; po1 = n1;
                cur ^= 1;
                __syncwarp();
            }

            eC0[0] = eN0[0]; eC0[1] = eN0[1]; eC0[2] = eN0[2]; eC0[3] = eN0[3];
            eC1[0] = eN1[0]; eC1[1] = eN1[1]; eC1[2] = eN1[2]; eC1[3] = eN1[3];
            rn0 = rrn0; rn1 = rrn1;
            mkC = mkN; mkN = mkN2;
            if (hv) { rrn0 = l0; rrn1 = l1; mkN2 = lm; }
        }
        if (act) { fx[d0] = po0; fx[d1] = po1; }
        if (lane == 0) offsm[0] = offset;
    } else {
        unsigned long long E2[52];
        {
#pragma unroll
            for (int dd = 0; dd < H_; dd++)
                E2[dd] = pk2(__expf(transition[dd * H_ + c0]), __expf(transition[dd * H_ + c1]));
        }
        float ro0 = __expf(transition[STOP_ * H_ + c0]);
        float ro1 = __expf(transition[STOP_ * H_ + c1]);
        float offset = 0.0f;

        float eC0[4], eC1[4];
        float4 rn0, rn1, rrn0, rrn1, mkC, mkN, mkN2;
        {
            float4 a = *reinterpret_cast<const float4*>(e0 + 127 * 4);
            float4 c = *reinterpret_cast<const float4*>(e1 + 127 * 4);
            eC0[0] = __expf(a.x); eC0[1] = __expf(a.y); eC0[2] = __expf(a.z); eC0[3] = __expf(a.w);
            eC1[0] = __expf(c.x); eC1[1] = __expf(c.y); eC1[2] = __expf(c.z); eC1[3] = __expf(c.w);
            rn0  = *reinterpret_cast<const float4*>(e0 + 126 * 4);
            rn1  = *reinterpret_cast<const float4*>(e1 + 126 * 4);
            rrn0 = *reinterpret_cast<const float4*>(e0 + 125 * 4);
            rrn1 = *reinterpret_cast<const float4*>(e1 + 125 * 4);
            mkC = m4[127]; mkN = m4[126]; mkN2 = m4[125];
        }
        __syncwarp();

        int cur = 0;
        for (int tb = 127; tb >= 64; tb--) {
            float4 l0, l1, lm;
            const bool hv = (tb - 3 >= 64);
            if (hv) {
                l0 = *reinterpret_cast<const float4*>(e0 + (tb - 3) * 4);
                l1 = *reinterpret_cast<const float4*>(e1 + (tb - 3) * 4);
                lm = m4[tb - 3];
            }
            float eN0[4], eN1[4];
            eN0[0] = __expf(rn0.x); eN0[1] = __expf(rn0.y); eN0[2] = __expf(rn0.z); eN0[3] = __expf(rn0.w);
            eN1[0] = __expf(rn1.x); eN1[1] = __expf(rn1.y); eN1[2] = __expf(rn1.z); eN1[3] = __expf(rn1.w);

            float rinv = 1.0f;
            if (tb != 127) {
                float r = __shfl_sync(FULL, ro0, 0);
                rinv = 1.0f / r;
                offset += __logf(r);
            }
            float mk[4] = {mkC.x, mkC.y, mkC.z, mkC.w};

#pragma unroll
            for (int si = 0; si < 4; si++) {
                const int s = 3 - si;
                float w0 = eC0[s] * ro0;
                float w1 = eC1[s] * ro1;
                *reinterpret_cast<float4*>(&myb[cur][4 * lane]) = make_float4(w0, w0, w1, w1);
                __syncwarp();
                const ulonglong2* u = reinterpret_cast<const ulonglong2*>(&myb[cur][0]);
                unsigned long long A0 = 0ULL, A1 = 0ULL, A2 = 0ULL, A3 = 0ULL;
#pragma unroll
                for (int q = 0; q < 26; q++) {
                    ulonglong2 uq = u[q];
                    if (q & 1) { A2 = fma2(E2[2 * q], uq.x, A2); A3 = fma2(E2[2 * q + 1], uq.y, A3); }
                    else       { A0 = fma2(E2[2 * q], uq.x, A0); A1 = fma2(E2[2 * q + 1], uq.y, A1); }
                }
                unsigned long long S2 = add2(add2(A0, A1), add2(A2, A3));
                float S0, S1;
                upk2(S2, S0, S1);
                bool on = (mk[s] > 0.5f);
                float n0 = on ? S0 : ro0;
                float n1 = on ? S1 : ro1;
                if (s == 3) { n0 *= rinv; n1 *= rinv; }
                ro0 = n0; ro1 = n1;
                cur ^= 1;
            }

            eC0[0] = eN0[0]; eC0[1] = eN0[1]; eC0[2] = eN0[2]; eC0[3] = eN0[3];
            eC1[0] = eN1[0]; eC1[1] = eN1[1]; eC1[2] = eN1[2]; eC1[3] = eN1[3];
            rn0 = rrn0; rn1 = rrn1;
            mkC = mkN; mkN = mkN2;
            if (hv) { rrn0 = l0; rrn1 = l1; mkN2 = lm; }
        }
        if (act) { bx[d0] = ro0; bx[d1] = ro1; }
        if (lane == 0) offsm[1] = offset;
    }

    __syncthreads();
    if (w == 0) {
        float term = act ? (fx[d0] * bx[d0] + fx[d1] * bx[d1]) : 0.0f;
#pragma unroll
        for (int s = 16; s > 0; s >>= 1) term += __shfl_xor_sync(FULL, term, s);
        if (lane == 0) {
            float goldT = goldsm[0] + goldsm[1];
            float msumT = msumsm[0] + msumsm[1];
            int lp = (int)(msumT + 0.5f);
            int lt = (lp > 0) ? tags[base + lp - 1] : START_;
            goldT += transition[STOP_ * H_ + lt];
            g_diff[b] = offsm[0] + offsm[1] + __logf(term) - goldT;
        }
    }
}

// ============================================================
// Kernel 3: mean over batches
// ============================================================
__global__ void __launch_bounds__(64)
finalize_kernel(float* __restrict__ out) {
    __shared__ float red[64];
    int tid = threadIdx.x;
    red[tid] = g_diff[tid];
    __syncthreads();
    for (int s = 32; s > 0; s >>= 1) { if (tid < s) red[tid] += red[tid + s]; __syncthreads(); }
    if (tid == 0) out[0] = red[0] * (1.0f / (float)B_);
}

// ============================================================
// launch
// ============================================================
extern "C" void kernel_launch(void* const* d_in, const int* in_sizes, int n_in,
                              void* d_out, int out_size) {
    const float* feat  = (const float*)d_in[0];
    const float* W     = (const float*)d_in[1];
    const float* bias  = (const float*)d_in[2];
    const float* trans = (const float*)d_in[3];
    const float* masks = (const float*)d_in[4];
    const int*   tags  = (const int*)d_in[5];
    float* out = (float*)d_out;

    emit_gemm_kernel<<<128, 256>>>(feat, W, bias);
    crf_scan_kernel<<<B_, 64>>>(trans, masks, tags);
    finalize_kernel<<<1, 64>>>(out);
}

// round 15
// speedup vs baseline: 1.1442x; 1.0304x over previous
#include <cuda_runtime.h>
#include <cuda_bf16.h>
#include <cstdint>

#define B_    64
#define T_    512
#define F_    1024
#define H_    52
#define START_ 50
#define STOP_  51

__device__ float g_emitT[(size_t)B_ * H_ * T_]; // emit transposed [b][h][t]
__device__ float g_diff[B_];

// ---------- packed fp32x2 helpers (scan) ----------
__device__ __forceinline__ unsigned long long pk2(float lo, float hi) {
    unsigned long long d;
    asm("mov.b64 %0, {%1, %2};" : "=l"(d) : "r"(__float_as_uint(lo)), "r"(__float_as_uint(hi)));
    return d;
}
__device__ __forceinline__ void upk2(unsigned long long v, float& lo, float& hi) {
    unsigned int a, b;
    asm("mov.b64 {%0, %1}, %2;" : "=r"(a), "=r"(b) : "l"(v));
    lo = __uint_as_float(a); hi = __uint_as_float(b);
}
__device__ __forceinline__ unsigned long long fma2(unsigned long long a, unsigned long long b,
                                                   unsigned long long c) {
    unsigned long long d;
    asm("fma.rn.f32x2 %0, %1, %2, %3;" : "=l"(d) : "l"(a), "l"(b), "l"(c));
    return d;
}
__device__ __forceinline__ unsigned long long add2(unsigned long long a, unsigned long long b) {
    unsigned long long d;
    asm("add.rn.f32x2 %0, %1, %2;" : "=l"(d) : "l"(a), "l"(b));
    return d;
}

// ---------- tf32 mma (Ampere-class, valid on sm_103) ----------
__device__ __forceinline__ void mma_tf32(float* d, const uint32_t* a, uint32_t b0, uint32_t b1) {
    asm volatile(
        "mma.sync.aligned.m16n8k8.row.col.f32.tf32.tf32.f32 "
        "{%0,%1,%2,%3}, {%4,%5,%6,%7}, {%8,%9}, {%0,%1,%2,%3};"
        : "+f"(d[0]), "+f"(d[1]), "+f"(d[2]), "+f"(d[3])
        : "r"(a[0]), "r"(a[1]), "r"(a[2]), "r"(a[3]), "r"(b0), "r"(b1));
}

// ============================================================
// Kernel 1: emit = features @ W^T + b via tf32 mma.sync.
// 256 blocks x 256 threads, 128-row tiles => 2 CTAs/SM (latency
// cross-fill). Warp w owns rows [16w,16w+16): 1 m16 x 7 n8 tiles.
// K staged in 32-chunks. Output transposed via smem staging.
// ============================================================
#define SA_ST 136   // 136 % 32 == 8 -> frag loads conflict-free
#define SB_ST 73

__global__ void __launch_bounds__(256, 2)
emit_gemm_kernel(const float* __restrict__ feat, const float* __restrict__ W,
                 const float* __restrict__ bias) {
    __shared__ float sA[32 * SA_ST];   // [k][row 0..127(+pad)]  17.4KB
    __shared__ float sB[32 * SB_ST];   // [k][n 0..55(+pad)]      9.3KB

    const int tid = threadIdx.x;
    const int lane = tid & 31;
    const int w = tid >> 5;            // warp 0..7
    const int a_ = lane >> 2;          // 0..7
    const int b_ = lane & 3;           // 0..3
    const int blockRow = blockIdx.x * 128;

    float c[7][4];
#pragma unroll
    for (int nt = 0; nt < 7; nt++)
#pragma unroll
        for (int j = 0; j < 4; j++) c[nt][j] = 0.0f;

    float4 fv[4];
    float  wv[7];

    const int lrow = tid >> 1;         // 0..127
    const int lj4  = (tid & 1) * 4;    // float4 index base 0 or 4

    auto load_chunk = [&](int k0) {
#pragma unroll
        for (int it = 0; it < 4; it++) {
            fv[it] = *reinterpret_cast<const float4*>(
                &feat[(size_t)(blockRow + lrow) * F_ + k0 + (lj4 + it) * 4]);
        }
#pragma unroll
        for (int it = 0; it < 7; it++) {
            int hh = w + it * 8;       // 0..55
            wv[it] = (hh < H_) ? W[(size_t)hh * F_ + k0 + lane] : 0.0f;
        }
    };
    auto store_chunk = [&]() {
#pragma unroll
        for (int it = 0; it < 4; it++) {
            int kb = (lj4 + it) * 4;
            sA[(kb + 0) * SA_ST + lrow] = fv[it].x;
            sA[(kb + 1) * SA_ST + lrow] = fv[it].y;
            sA[(kb + 2) * SA_ST + lrow] = fv[it].z;
            sA[(kb + 3) * SA_ST + lrow] = fv[it].w;
        }
#pragma unroll
        for (int it = 0; it < 7; it++) sB[lane * SB_ST + w + it * 8] = wv[it];
    };
    auto compute = [&]() {
        const int rb = w * 16;
#pragma unroll
        for (int ks = 0; ks < 4; ks++) {
            const int kb = ks * 8;
            uint32_t A[4];
            A[0] = __float_as_uint(sA[(kb + b_) * SA_ST + rb + a_]);
            A[1] = __float_as_uint(sA[(kb + b_) * SA_ST + rb + a_ + 8]);
            A[2] = __float_as_uint(sA[(kb + b_ + 4) * SA_ST + rb + a_]);
            A[3] = __float_as_uint(sA[(kb + b_ + 4) * SA_ST + rb + a_ + 8]);
#pragma unroll
            for (int nt = 0; nt < 7; nt++) {
                uint32_t B0 = __float_as_uint(sB[(kb + b_) * SB_ST + nt * 8 + a_]);
                uint32_t B1 = __float_as_uint(sB[(kb + b_ + 4) * SB_ST + nt * 8 + a_]);
                mma_tf32(c[nt], A, B0, B1);
            }
        }
    };

    load_chunk(0);
    for (int k0 = 0; k0 < F_; k0 += 32) {
        __syncthreads();
        store_chunk();
        __syncthreads();
        if (k0 + 32 < F_) load_chunk(k0 + 32);
        compute();
    }

    // ---- epilogue: stage [col][row] in smem, coalesced transposed store ----
    const int bIdx = blockRow >> 9;
    const int t0 = blockRow & 511;
    const size_t bbase = (size_t)bIdx * (H_ * T_);
    float* stage = sA;                 // 28*130 = 3640 <= 4352 floats

    __syncthreads();
#pragma unroll 1
    for (int pass = 0; pass < 2; pass++) {
        const int cb = pass * 28;
#pragma unroll
        for (int nt = 0; nt < 7; nt++)
#pragma unroll
            for (int j = 0; j < 4; j++) {
                int col = nt * 8 + 2 * b_ + (j & 1);
                int row = w * 16 + a_ + ((j >> 1) * 8);
                if (col >= cb && col < cb + 28)
                    stage[(col - cb) * 130 + row] = c[nt][j];
            }
        __syncthreads();
        for (int e = tid; e < 28 * 128; e += 256) {
            int cc = e >> 7, r = e & 127;
            int colg = cb + cc;
            if (colg < H_)
                g_emitT[bbase + (size_t)colg * T_ + t0 + r] =
                    stage[cc * 130 + r] + __ldg(&bias[colg]);
        }
        __syncthreads();
    }
}

// ============================================================
// Kernel 2: CRF forward via BIDIRECTIONAL scan (R13 best config,
// de-diverged hot loop, unchanged).
// ============================================================
__global__ void __launch_bounds__(64, 1)
crf_scan_kernel(const float* __restrict__ transition, const float* __restrict__ masks,
                const int* __restrict__ tags) {
    const int b = blockIdx.x;
    const int tid = threadIdx.x;
    const int w = tid >> 5;
    const int lane = tid & 31;
    const bool act = (lane < 26);
    const int d0 = 2 * lane;
    const int d1 = 2 * lane + 1;
    const int c0 = (d0 < H_) ? d0 : 0;
    const int c1 = (d1 < H_) ? d1 : 0;
    const int base = b * T_;
    const unsigned FULL = 0xFFFFFFFFu;

    __shared__ __align__(16) float bufs[2][2][128];
    __shared__ float fx[52], bx[52];
    __shared__ float offsm[2], goldsm[2], msumsm[2];

    const float* embB = &g_emitT[(size_t)b * (H_ * T_)];

    float gold = 0.0f, msum = 0.0f;
    for (int t = tid; t < T_; t += 64) {
        float mk = masks[base + t];
        int tg = tags[base + t];
        int pv = (t == 0) ? START_ : tags[base + t - 1];
        gold += mk * (embB[(size_t)tg * T_ + t] + transition[tg * H_ + pv]);
        msum += mk;
    }
#pragma unroll
    for (int s = 16; s > 0; s >>= 1) {
        gold += __shfl_xor_sync(FULL, gold, s);
        msum += __shfl_xor_sync(FULL, msum, s);
    }
    if (lane == 0) { goldsm[w] = gold; msumsm[w] = msum; }

    const float* e0 = embB + (size_t)c0 * T_;
    const float* e1 = embB + (size_t)c1 * T_;
    const float4* m4 = reinterpret_cast<const float4*>(&masks[base]);
    float (*myb)[128] = bufs[w];

    if (w == 0) {
        unsigned long long E2[52];
        {
            const float* r0 = &transition[c0 * H_];
            const float* r1 = &transition[c1 * H_];
#pragma unroll
            for (int s = 0; s < H_; s++) E2[s] = pk2(__expf(r0[s]), __expf(r1[s]));
        }
        float po0 = (d0 == START_) ? 1.0f : 0.0f;
        float po1 = 0.0f;
        *reinterpret_cast<float4*>(&myb[0][4 * lane]) = make_float4(po0, po0, po1, po1);
        float offset = 0.0f;

        float eC0[4], eC1[4];
        float4 rn0, rn1, rrn0, rrn1, mkC, mkN, mkN2;
        {
            float4 a = *reinterpret_cast<const float4*>(e0);
            float4 c = *reinterpret_cast<const float4*>(e1);
            eC0[0] = __expf(a.x); eC0[1] = __expf(a.y); eC0[2] = __expf(a.z); eC0[3] = __expf(a.w);
            eC1[0] = __expf(c.x); eC1[1] = __expf(c.y); eC1[2] = __expf(c.z); eC1[3] = __expf(c.w);
            rn0  = *reinterpret_cast<const float4*>(e0 + 4);
            rn1  = *reinterpret_cast<const float4*>(e1 + 4);
            rrn0 = *reinterpret_cast<const float4*>(e0 + 8);
            rrn1 = *reinterpret_cast<const float4*>(e1 + 8);
            mkC = m4[0]; mkN = m4[1]; mkN2 = m4[2];
        }
        __syncwarp();

        int cur = 0;
        for (int tb = 0; tb < 64; tb++) {
            float4 l0, l1, lm;
            const bool hv = (tb + 3 < 64);
            if (hv) {
                l0 = *reinterpret_cast<const float4*>(e0 + (tb + 3) * 4);
                l1 = *reinterpret_cast<const float4*>(e1 + (tb + 3) * 4);
                lm = m4[tb + 3];
            }
            float eN0[4], eN1[4];
            eN0[0] = __expf(rn0.x); eN0[1] = __expf(rn0.y); eN0[2] = __expf(rn0.z); eN0[3] = __expf(rn0.w);
            eN1[0] = __expf(rn1.x); eN1[1] = __expf(rn1.y); eN1[2] = __expf(rn1.z); eN1[3] = __expf(rn1.w);

            float rinv = 1.0f;
            if (tb) {
                float r = __shfl_sync(FULL, po0, 0);
                rinv = 1.0f / r;
                offset += __logf(r);
            }
            float mk[4] = {mkC.x, mkC.y, mkC.z, mkC.w};

#pragma unroll
            for (int s = 0; s < 4; s++) {
                const ulonglong2* u = reinterpret_cast<const ulonglong2*>(&myb[cur][0]);
                unsigned long long A0 = 0ULL, A1 = 0ULL, A2 = 0ULL, A3 = 0ULL;
#pragma unroll
                for (int q = 0; q < 26; q++) {
                    ulonglong2 uq = u[q];
                    if (q & 1) { A2 = fma2(E2[2 * q], uq.x, A2); A3 = fma2(E2[2 * q + 1], uq.y, A3); }
                    else       { A0 = fma2(E2[2 * q], uq.x, A0); A1 = fma2(E2[2 * q + 1], uq.y, A1); }
                }
                unsigned long long S2 = add2(add2(A0, A1), add2(A2, A3));
                float S0, S1;
                upk2(S2, S0, S1);
                bool on = (mk[s] > 0.5f);
                float n0 = on ? S0 * eC0[s] : po0;
                float n1 = on ? S1 * eC1[s] : po1;
                if (s == 0) { n0 *= rinv; n1 *= rinv; }
                *reinterpret_cast<float4*>(&myb[cur ^ 1][4 * lane]) = make_float4(n0, n0, n1, n1);
                po0 = n0; po1 = n1;
                cur ^= 1;
                __syncwarp();
            }

            eC0[0] = eN0[0]; eC0[1] = eN0[1]; eC0[2] = eN0[2]; eC0[3] = eN0[3];
            eC1[0] = eN1[0]; eC1[1] = eN1[1]; eC1[2] = eN1[2]; eC1[3] = eN1[3];
            rn0 = rrn0; rn1 = rrn1;
            mkC = mkN; mkN = mkN2;
            if (hv) { rrn0 = l0; rrn1 = l1; mkN2 = lm; }
        }
        if (act) { fx[d0] = po0; fx[d1] = po1; }
        if (lane == 0) offsm[0] = offset;
    } else {
        unsigned long long E2[52];
        {
#pragma unroll
            for (int dd = 0; dd < H_; dd++)
                E2[dd] = pk2(__expf(transition[dd * H_ + c0]), __expf(transition[dd * H_ + c1]));
        }
        float ro0 = __expf(transition[STOP_ * H_ + c0]);
        float ro1 = __expf(transition[STOP_ * H_ + c1]);
        float offset = 0.0f;

        float eC0[4], eC1[4];
        float4 rn0, rn1, rrn0, rrn1, mkC, mkN, mkN2;
        {
            float4 a = *reinterpret_cast<const float4*>(e0 + 127 * 4);
            float4 c = *reinterpret_cast<const float4*>(e1 + 127 * 4);
            eC0[0] = __expf(a.x); eC0[1] = __expf(a.y); eC0[2] = __expf(a.z); eC0[3] = __expf(a.w);
            eC1[0] = __expf(c.x); eC1[1] = __expf(c.y); eC1[2] = __expf(c.z); eC1[3] = __expf(c.w);
            rn0  = *reinterpret_cast<const float4*>(e0 + 126 * 4);
            rn1  = *reinterpret_cast<const float4*>(e1 + 126 * 4);
            rrn0 = *reinterpret_cast<const float4*>(e0 + 125 * 4);
            rrn1 = *reinterpret_cast<const float4*>(e1 + 125 * 4);
            mkC = m4[127]; mkN = m4[126]; mkN2 = m4[125];
        }
        __syncwarp();

        int cur = 0;
        for (int tb = 127; tb >= 64; tb--) {
            float4 l0, l1, lm;
            const bool hv = (tb - 3 >= 64);
            if (hv) {
                l0 = *reinterpret_cast<const float4*>(e0 + (tb - 3) * 4);
                l1 = *reinterpret_cast<const float4*>(e1 + (tb - 3) * 4);
                lm = m4[tb - 3];
            }
            float eN0[4], eN1[4];
            eN0[0] = __expf(rn0.x); eN0[1] = __expf(rn0.y); eN0[2] = __expf(rn0.z); eN0[3] = __expf(rn0.w);
            eN1[0] = __expf(rn1.x); eN1[1] = __expf(rn1.y); eN1[2] = __expf(rn1.z); eN1[3] = __expf(rn1.w);

            float rinv = 1.0f;
            if (tb != 127) {
                float r = __shfl_sync(FULL, ro0, 0);
                rinv = 1.0f / r;
                offset += __logf(r);
            }
            float mk[4] = {mkC.x, mkC.y, mkC.z, mkC.w};

#pragma unroll
            for (int si = 0; si < 4; si++) {
                const int s = 3 - si;
                float w0 = eC0[s] * ro0;
                float w1 = eC1[s] * ro1;
                *reinterpret_cast<float4*>(&myb[cur][4 * lane]) = make_float4(w0, w0, w1, w1);
                __syncwarp();
                const ulonglong2* u = reinterpret_cast<const ulonglong2*>(&myb[cur][0]);
                unsigned long long A0 = 0ULL, A1 = 0ULL, A2 = 0ULL, A3 = 0ULL;
#pragma unroll
                for (int q = 0; q < 26; q++) {
                    ulonglong2 uq = u[q];
                    if (q & 1) { A2 = fma2(E2[2 * q], uq.x, A2); A3 = fma2(E2[2 * q + 1], uq.y, A3); }
                    else       { A0 = fma2(E2[2 * q], uq.x, A0); A1 = fma2(E2[2 * q + 1], uq.y, A1); }
                }
                unsigned long long S2 = add2(add2(A0, A1), add2(A2, A3));
                float S0, S1;
                upk2(S2, S0, S1);
                bool on = (mk[s] > 0.5f);
                float n0 = on ? S0 : ro0;
                float n1 = on ? S1 : ro1;
                if (s == 3) { n0 *= rinv; n1 *= rinv; }
                ro0 = n0; ro1 = n1;
                cur ^= 1;
            }

            eC0[0] = eN0[0]; eC0[1] = eN0[1]; eC0[2] = eN0[2]; eC0[3] = eN0[3];
            eC1[0] = eN1[0]; eC1[1] = eN1[1]; eC1[2] = eN1[2]; eC1[3] = eN1[3];
            rn0 = rrn0; rn1 = rrn1;
            mkC = mkN; mkN = mkN2;
            if (hv) { rrn0 = l0; rrn1 = l1; mkN2 = lm; }
        }
        if (act) { bx[d0] = ro0; bx[d1] = ro1; }
        if (lane == 0) offsm[1] = offset;
    }

    __syncthreads();
    if (w == 0) {
        float term = act ? (fx[d0] * bx[d0] + fx[d1] * bx[d1]) : 0.0f;
#pragma unroll
        for (int s = 16; s > 0; s >>= 1) term += __shfl_xor_sync(FULL, term, s);
        if (lane == 0) {
            float goldT = goldsm[0] + goldsm[1];
            float msumT = msumsm[0] + msumsm[1];
            int lp = (int)(msumT + 0.5f);
            int lt = (lp > 0) ? tags[base + lp - 1] : START_;
            goldT += transition[STOP_ * H_ + lt];
            g_diff[b] = offsm[0] + offsm[1] + __logf(term) - goldT;
        }
    }
}

// ============================================================
// Kernel 3: mean over batches
// ============================================================
__global__ void __launch_bounds__(64)
finalize_kernel(float* __restrict__ out) {
    __shared__ float red[64];
    int tid = threadIdx.x;
    red[tid] = g_diff[tid];
    __syncthreads();
    for (int s = 32; s > 0; s >>= 1) { if (tid < s) red[tid] += red[tid + s]; __syncthreads(); }
    if (tid == 0) out[0] = red[0] * (1.0f / (float)B_);
}

// ============================================================
// launch
// ============================================================
extern "C" void kernel_launch(void* const* d_in, const int* in_sizes, int n_in,
                              void* d_out, int out_size) {
    const float* feat  = (const float*)d_in[0];
    const float* W     = (const float*)d_in[1];
    const float* bias  = (const float*)d_in[2];
    const float* trans = (const float*)d_in[3];
    const float* masks = (const float*)d_in[4];
    const int*   tags  = (const int*)d_in[5];
    float* out = (float*)d_out;

    emit_gemm_kernel<<<256, 256>>>(feat, W, bias);
    crf_scan_kernel<<<B_, 64>>>(trans, masks, tags);
    finalize_kernel<<<1, 64>>>(out);
}

// round 16
// speedup vs baseline: 1.3627x; 1.1909x over previous
#include <cuda_runtime.h>
#include <cuda_bf16.h>
#include <cstdint>

#define B_    64
#define T_    512
#define F_    1024
#define H_    52
#define START_ 50
#define STOP_  51

__device__ float g_emitT[(size_t)B_ * H_ * T_]; // emit transposed [b][h][t]
__device__ float g_diff[B_];

// ---------- packed fp32x2 helpers (scan) ----------
__device__ __forceinline__ unsigned long long pk2(float lo, float hi) {
    unsigned long long d;
    asm("mov.b64 %0, {%1, %2};" : "=l"(d) : "r"(__float_as_uint(lo)), "r"(__float_as_uint(hi)));
    return d;
}
__device__ __forceinline__ void upk2(unsigned long long v, float& lo, float& hi) {
    unsigned int a, b;
    asm("mov.b64 {%0, %1}, %2;" : "=r"(a), "=r"(b) : "l"(v));
    lo = __uint_as_float(a); hi = __uint_as_float(b);
}
__device__ __forceinline__ unsigned long long fma2(unsigned long long a, unsigned long long b,
                                                   unsigned long long c) {
    unsigned long long d;
    asm("fma.rn.f32x2 %0, %1, %2, %3;" : "=l"(d) : "l"(a), "l"(b), "l"(c));
    return d;
}
__device__ __forceinline__ unsigned long long add2(unsigned long long a, unsigned long long b) {
    unsigned long long d;
    asm("add.rn.f32x2 %0, %1, %2;" : "=l"(d) : "l"(a), "l"(b));
    return d;
}
__device__ __forceinline__ uint32_t smem_u32(const void* p) {
    uint32_t a;
    asm("{ .reg .u64 t; cvta.to.shared.u64 t, %1; cvt.u32.u64 %0, t; }" : "=r"(a) : "l"(p));
    return a;
}

// ---------- tf32 mma (Ampere-class, valid on sm_103) ----------
__device__ __forceinline__ void mma_tf32(float* d, const uint32_t* a, uint32_t b0, uint32_t b1) {
    asm volatile(
        "mma.sync.aligned.m16n8k8.row.col.f32.tf32.tf32.f32 "
        "{%0,%1,%2,%3}, {%4,%5,%6,%7}, {%8,%9}, {%0,%1,%2,%3};"
        : "+f"(d[0]), "+f"(d[1]), "+f"(d[2]), "+f"(d[3])
        : "r"(a[0]), "r"(a[1]), "r"(a[2]), "r"(a[3]), "r"(b0), "r"(b1));
}

// ============================================================
// Kernel 1: emit = features @ W^T + b via tf32 mma.sync with a
// 4-stage cp.async pipeline (3 chunks of K=32 permanently in
// flight -> DRAM latency hidden). 256 blocks x 256 threads,
// 128-row tiles. Layout [row][k], stride 36 (bank = 4a+b unique).
// ============================================================
#define SRK 36                         // row stride in floats
#define A_FL (128 * SRK)               // 4608 floats
#define B_FL (56 * SRK)                // 2016 floats
#define STAGE_FL (A_FL + B_FL)         // 6624 floats
#define NSTAGE 4
#define GEMM_SMEM_BYTES (NSTAGE * STAGE_FL * 4)   // 105984 B

__global__ void __launch_bounds__(256, 1)
emit_gemm_kernel(const float* __restrict__ feat, const float* __restrict__ W,
                 const float* __restrict__ bias) {
    extern __shared__ __align__(16) float smem[];
    const uint32_t su = smem_u32(smem);

    const int tid = threadIdx.x;
    const int lane = tid & 31;
    const int w = tid >> 5;            // warp 0..7
    const int a_ = lane >> 2;          // 0..7
    const int b_ = lane & 3;           // 0..3
    const int blockRow = blockIdx.x * 128;

    float c[7][4];
#pragma unroll
    for (int nt = 0; nt < 7; nt++)
#pragma unroll
        for (int j = 0; j < 4; j++) c[nt][j] = 0.0f;

    // cp.async index precompute
    const int arow = tid >> 1;                 // 0..127
    const int akq  = (tid & 1) * 4;            // k-quad base: 0 or 4

    auto cp_stage = [&](int ch, int st) {
        const int k0 = ch * 32;
        // A: 128 rows x 8 k-quads; 4 per thread
        {
            const float* src = &feat[(size_t)(blockRow + arow) * F_ + k0];
            uint32_t dst = su + (uint32_t)(st * STAGE_FL + arow * SRK) * 4;
#pragma unroll
            for (int it = 0; it < 4; it++) {
                int kq = akq + it;             // interleave halves? akq in {0,4}: quads akq..akq+3
                asm volatile("cp.async.cg.shared.global [%0], [%1], 16;"
                             :: "r"(dst + (uint32_t)(kq * 4) * 4), "l"(src + kq * 4));
            }
        }
        // B: 52 valid rows x 8 k-quads = 416 ops; <=2 per thread
        {
#pragma unroll
            for (int it = 0; it < 2; it++) {
                int idx = tid + it * 256;
                int n = idx >> 3;
                int kq = idx & 7;
                if (n < H_) {
                    uint32_t dst = su + (uint32_t)(st * STAGE_FL + A_FL + n * SRK + kq * 4) * 4;
                    const float* src = &W[(size_t)n * F_ + k0 + kq * 4];
                    asm volatile("cp.async.cg.shared.global [%0], [%1], 16;"
                                 :: "r"(dst), "l"(src));
                }
            }
        }
        asm volatile("cp.async.commit_group;" ::: "memory");
    };

    auto compute = [&](int st) {
        const float* sA = smem + st * STAGE_FL;
        const float* sB = sA + A_FL;
        const int rb = w * 16;
#pragma unroll
        for (int ks = 0; ks < 4; ks++) {
            const int kb = ks * 8;
            uint32_t A[4];
            A[0] = __float_as_uint(sA[(rb + a_) * SRK + kb + b_]);
            A[1] = __float_as_uint(sA[(rb + a_ + 8) * SRK + kb + b_]);
            A[2] = __float_as_uint(sA[(rb + a_) * SRK + kb + b_ + 4]);
            A[3] = __float_as_uint(sA[(rb + a_ + 8) * SRK + kb + b_ + 4]);
#pragma unroll
            for (int nt = 0; nt < 7; nt++) {
                uint32_t B0 = __float_as_uint(sB[(nt * 8 + a_) * SRK + kb + b_]);
                uint32_t B1 = __float_as_uint(sB[(nt * 8 + a_) * SRK + kb + b_ + 4]);
                mma_tf32(c[nt], A, B0, B1);
            }
        }
    };

    // zero B pad rows (n 52..55) once per stage to avoid NaN reads
    for (int s = 0; s < NSTAGE; s++)
        for (int e = tid; e < 4 * SRK; e += 256)
            smem[s * STAGE_FL + A_FL + 52 * SRK + e] = 0.0f;
    __syncthreads();

    // prologue: stages 0..2 in flight
    cp_stage(0, 0);
    cp_stage(1, 1);
    cp_stage(2, 2);

#pragma unroll 1
    for (int ch = 0; ch < 32; ch++) {
        asm volatile("cp.async.wait_group 2;" ::: "memory");   // chunk ch landed
        __syncthreads();                                        // visible to all; buf (ch+3)%4 reads done
        if (ch + 3 < 32) cp_stage(ch + 3, (ch + 3) & 3);
        else asm volatile("cp.async.commit_group;" ::: "memory");
        compute(ch & 3);
    }

    // ---- epilogue: stage [col][row] in smem, coalesced transposed store ----
    const int bIdx = blockRow >> 9;
    const int t0 = blockRow & 511;
    const size_t bbase = (size_t)bIdx * (H_ * T_);
    float* stage = smem;               // 28*130 = 3640 floats

    asm volatile("cp.async.wait_group 0;" ::: "memory");
    __syncthreads();
#pragma unroll 1
    for (int pass = 0; pass < 2; pass++) {
        const int cb = pass * 28;
#pragma unroll
        for (int nt = 0; nt < 7; nt++)
#pragma unroll
            for (int j = 0; j < 4; j++) {
                int col = nt * 8 + 2 * b_ + (j & 1);
                int row = w * 16 + a_ + ((j >> 1) * 8);
                if (col >= cb && col < cb + 28)
                    stage[(col - cb) * 130 + row] = c[nt][j];
            }
        __syncthreads();
        for (int e = tid; e < 28 * 128; e += 256) {
            int cc = e >> 7, r = e & 127;
            int colg = cb + cc;
            if (colg < H_)
                g_emitT[bbase + (size_t)colg * T_ + t0 + r] =
                    stage[cc * 130 + r] + __ldg(&bias[colg]);
        }
        __syncthreads();
    }
}

// ============================================================
// Kernel 2: CRF forward via BIDIRECTIONAL scan (R13 best config,
// de-diverged hot loop, unchanged).
// ============================================================
__global__ void __launch_bounds__(64, 1)
crf_scan_kernel(const float* __restrict__ transition, const float* __restrict__ masks,
                const int* __restrict__ tags) {
    const int b = blockIdx.x;
    const int tid = threadIdx.x;
    const int w = tid >> 5;
    const int lane = tid & 31;
    const bool act = (lane < 26);
    const int d0 = 2 * lane;
    const int d1 = 2 * lane + 1;
    const int c0 = (d0 < H_) ? d0 : 0;
    const int c1 = (d1 < H_) ? d1 : 0;
    const int base = b * T_;
    const unsigned FULL = 0xFFFFFFFFu;

    __shared__ __align__(16) float bufs[2][2][128];
    __shared__ float fx[52], bx[52];
    __shared__ float offsm[2], goldsm[2], msumsm[2];

    const float* embB = &g_emitT[(size_t)b * (H_ * T_)];

    float gold = 0.0f, msum = 0.0f;
    for (int t = tid; t < T_; t += 64) {
        float mk = masks[base + t];
        int tg = tags[base + t];
        int pv = (t == 0) ? START_ : tags[base + t - 1];
        gold += mk * (embB[(size_t)tg * T_ + t] + transition[tg * H_ + pv]);
        msum += mk;
    }
#pragma unroll
    for (int s = 16; s > 0; s >>= 1) {
        gold += __shfl_xor_sync(FULL, gold, s);
        msum += __shfl_xor_sync(FULL, msum, s);
    }
    if (lane == 0) { goldsm[w] = gold; msumsm[w] = msum; }

    const float* e0 = embB + (size_t)c0 * T_;
    const float* e1 = embB + (size_t)c1 * T_;
    const float4* m4 = reinterpret_cast<const float4*>(&masks[base]);
    float (*myb)[128] = bufs[w];

    if (w == 0) {
        unsigned long long E2[52];
        {
            const float* r0 = &transition[c0 * H_];
            const float* r1 = &transition[c1 * H_];
#pragma unroll
            for (int s = 0; s < H_; s++) E2[s] = pk2(__expf(r0[s]), __expf(r1[s]));
        }
        float po0 = (d0 == START_) ? 1.0f : 0.0f;
        float po1 = 0.0f;
        *reinterpret_cast<float4*>(&myb[0][4 * lane]) = make_float4(po0, po0, po1, po1);
        float offset = 0.0f;

        float eC0[4], eC1[4];
        float4 rn0, rn1, rrn0, rrn1, mkC, mkN, mkN2;
        {
            float4 a = *reinterpret_cast<const float4*>(e0);
            float4 c = *reinterpret_cast<const float4*>(e1);
            eC0[0] = __expf(a.x); eC0[1] = __expf(a.y); eC0[2] = __expf(a.z); eC0[3] = __expf(a.w);
            eC1[0] = __expf(c.x); eC1[1] = __expf(c.y); eC1[2] = __expf(c.z); eC1[3] = __expf(c.w);
            rn0  = *reinterpret_cast<const float4*>(e0 + 4);
            rn1  = *reinterpret_cast<const float4*>(e1 + 4);
            rrn0 = *reinterpret_cast<const float4*>(e0 + 8);
            rrn1 = *reinterpret_cast<const float4*>(e1 + 8);
            mkC = m4[0]; mkN = m4[1]; mkN2 = m4[2];
        }
        __syncwarp();

        int cur = 0;
        for (int tb = 0; tb < 64; tb++) {
            float4 l0, l1, lm;
            const bool hv = (tb + 3 < 64);
            if (hv) {
                l0 = *reinterpret_cast<const float4*>(e0 + (tb + 3) * 4);
                l1 = *reinterpret_cast<const float4*>(e1 + (tb + 3) * 4);
                lm = m4[tb + 3];
            }
            float eN0[4], eN1[4];
            eN0[0] = __expf(rn0.x); eN0[1] = __expf(rn0.y); eN0[2] = __expf(rn0.z); eN0[3] = __expf(rn0.w);
            eN1[0] = __expf(rn1.x); eN1[1] = __expf(rn1.y); eN1[2] = __expf(rn1.z); eN1[3] = __expf(rn1.w);

            float rinv = 1.0f;
            if (tb) {
                float r = __shfl_sync(FULL, po0, 0);
                rinv = 1.0f / r;
                offset += __logf(r);
            }
            float mk[4] = {mkC.x, mkC.y, mkC.z, mkC.w};

#pragma unroll
            for (int s = 0; s < 4; s++) {
                const ulonglong2* u = reinterpret_cast<const ulonglong2*>(&myb[cur][0]);
                unsigned long long A0 = 0ULL, A1 = 0ULL, A2 = 0ULL, A3 = 0ULL;
#pragma unroll
                for (int q = 0; q < 26; q++) {
                    ulonglong2 uq = u[q];
                    if (q & 1) { A2 = fma2(E2[2 * q], uq.x, A2); A3 = fma2(E2[2 * q + 1], uq.y, A3); }
                    else       { A0 = fma2(E2[2 * q], uq.x, A0); A1 = fma2(E2[2 * q + 1], uq.y, A1); }
                }
                unsigned long long S2 = add2(add2(A0, A1), add2(A2, A3));
                float S0, S1;
                upk2(S2, S0, S1);
                bool on = (mk[s] > 0.5f);
                float n0 = on ? S0 * eC0[s] : po0;
                float n1 = on ? S1 * eC1[s] : po1;
                if (s == 0) { n0 *= rinv; n1 *= rinv; }
                *reinterpret_cast<float4*>(&myb[cur ^ 1][4 * lane]) = make_float4(n0, n0, n1, n1);
                po0 = n0; po1 = n1;
                cur ^= 1;
                __syncwarp();
            }

            eC0[0] = eN0[0]; eC0[1] = eN0[1]; eC0[2] = eN0[2]; eC0[3] = eN0[3];
            eC1[0] = eN1[0]; eC1[1] = eN1[1]; eC1[2] = eN1[2]; eC1[3] = eN1[3];
            rn0 = rrn0; rn1 = rrn1;
            mkC = mkN; mkN = mkN2;
            if (hv) { rrn0 = l0; rrn1 = l1; mkN2 = lm; }
        }
        if (act) { fx[d0] = po0; fx[d1] = po1; }
        if (lane == 0) offsm[0] = offset;
    } else {
        unsigned long long E2[52];
        {
#pragma unroll
            for (int dd = 0; dd < H_; dd++)
                E2[dd] = pk2(__expf(transition[dd * H_ + c0]), __expf(transition[dd * H_ + c1]));
        }
        float ro0 = __expf(transition[STOP_ * H_ + c0]);
        float ro1 = __expf(transition[STOP_ * H_ + c1]);
        float offset = 0.0f;

        float eC0[4], eC1[4];
        float4 rn0, rn1, rrn0, rrn1, mkC, mkN, mkN2;
        {
            float4 a = *reinterpret_cast<const float4*>(e0 + 127 * 4);
            float4 c = *reinterpret_cast<const float4*>(e1 + 127 * 4);
            eC0[0] = __expf(a.x); eC0[1] = __expf(a.y); eC0[2] = __expf(a.z); eC0[3] = __expf(a.w);
            eC1[0] = __expf(c.x); eC1[1] = __expf(c.y); eC1[2] = __expf(c.z); eC1[3] = __expf(c.w);
            rn0  = *reinterpret_cast<const float4*>(e0 + 126 * 4);
            rn1  = *reinterpret_cast<const float4*>(e1 + 126 * 4);
            rrn0 = *reinterpret_cast<const float4*>(e0 + 125 * 4);
            rrn1 = *reinterpret_cast<const float4*>(e1 + 125 * 4);
            mkC = m4[127]; mkN = m4[126]; mkN2 = m4[125];
        }
        __syncwarp();

        int cur = 0;
        for (int tb = 127; tb >= 64; tb--) {
            float4 l0, l1, lm;
            const bool hv = (tb - 3 >= 64);
            if (hv) {
                l0 = *reinterpret_cast<const float4*>(e0 + (tb - 3) * 4);
                l1 = *reinterpret_cast<const float4*>(e1 + (tb - 3) * 4);
                lm = m4[tb - 3];
            }
            float eN0[4], eN1[4];
            eN0[0] = __expf(rn0.x); eN0[1] = __expf(rn0.y); eN0[2] = __expf(rn0.z); eN0[3] = __expf(rn0.w);
            eN1[0] = __expf(rn1.x); eN1[1] = __expf(rn1.y); eN1[2] = __expf(rn1.z); eN1[3] = __expf(rn1.w);

            float rinv = 1.0f;
            if (tb != 127) {
                float r = __shfl_sync(FULL, ro0, 0);
                rinv = 1.0f / r;
                offset += __logf(r);
            }
            float mk[4] = {mkC.x, mkC.y, mkC.z, mkC.w};

#pragma unroll
            for (int si = 0; si < 4; si++) {
                const int s = 3 - si;
                float w0 = eC0[s] * ro0;
                float w1 = eC1[s] * ro1;
                *reinterpret_cast<float4*>(&myb[cur][4 * lane]) = make_float4(w0, w0, w1, w1);
                __syncwarp();
                const ulonglong2* u = reinterpret_cast<const ulonglong2*>(&myb[cur][0]);
                unsigned long long A0 = 0ULL, A1 = 0ULL, A2 = 0ULL, A3 = 0ULL;
#pragma unroll
                for (int q = 0; q < 26; q++) {
                    ulonglong2 uq = u[q];
                    if (q & 1) { A2 = fma2(E2[2 * q], uq.x, A2); A3 = fma2(E2[2 * q + 1], uq.y, A3); }
                    else       { A0 = fma2(E2[2 * q], uq.x, A0); A1 = fma2(E2[2 * q + 1], uq.y, A1); }
                }
                unsigned long long S2 = add2(add2(A0, A1), add2(A2, A3));
                float S0, S1;
                upk2(S2, S0, S1);
                bool on = (mk[s] > 0.5f);
                float n0 = on ? S0 : ro0;
                float n1 = on ? S1 : ro1;
                if (s == 3) { n0 *= rinv; n1 *= rinv; }
                ro0 = n0; ro1 = n1;
                cur ^= 1;
            }

            eC0[0] = eN0[0]; eC0[1] = eN0[1]; eC0[2] = eN0[2]; eC0[3] = eN0[3];
            eC1[0] = eN1[0]; eC1[1] = eN1[1]; eC1[2] = eN1[2]; eC1[3] = eN1[3];
            rn0 = rrn0; rn1 = rrn1;
            mkC = mkN; mkN = mkN2;
            if (hv) { rrn0 = l0; rrn1 = l1; mkN2 = lm; }
        }
        if (act) { bx[d0] = ro0; bx[d1] = ro1; }
        if (lane == 0) offsm[1] = offset;
    }

    __syncthreads();
    if (w == 0) {
        float term = act ? (fx[d0] * bx[d0] + fx[d1] * bx[d1]) : 0.0f;
#pragma unroll
        for (int s = 16; s > 0; s >>= 1) term += __shfl_xor_sync(FULL, term, s);
        if (lane == 0) {
            float goldT = goldsm[0] + goldsm[1];
            float msumT = msumsm[0] + msumsm[1];
            int lp = (int)(msumT + 0.5f);
            int lt = (lp > 0) ? tags[base + lp - 1] : START_;
            goldT += transition[STOP_ * H_ + lt];
            g_diff[b] = offsm[0] + offsm[1] + __logf(term) - goldT;
        }
    }
}

// ============================================================
// Kernel 3: mean over batches
// ============================================================
__global__ void __launch_bounds__(64)
finalize_kernel(float* __restrict__ out) {
    __shared__ float red[64];
    int tid = threadIdx.x;
    red[tid] = g_diff[tid];
    __syncthreads();
    for (int s = 32; s > 0; s >>= 1) { if (tid < s) red[tid] += red[tid + s]; __syncthreads(); }
    if (tid == 0) out[0] = red[0] * (1.0f / (float)B_);
}

// ============================================================
// launch
// ============================================================
extern "C" void kernel_launch(void* const* d_in, const int* in_sizes, int n_in,
                              void* d_out, int out_size) {
    const float* feat  = (const float*)d_in[0];
    const float* W     = (const float*)d_in[1];
    const float* bias  = (const float*)d_in[2];
    const float* trans = (const float*)d_in[3];
    const float* masks = (const float*)d_in[4];
    const int*   tags  = (const int*)d_in[5];
    float* out = (float*)d_out;

    cudaFuncSetAttribute(emit_gemm_kernel,
                         cudaFuncAttributeMaxDynamicSharedMemorySize, GEMM_SMEM_BYTES);

    emit_gemm_kernel<<<256, 256, GEMM_SMEM_BYTES>>>(feat, W, bias);
    crf_scan_kernel<<<B_, 64>>>(trans, masks, tags);
    finalize_kernel<<<1, 64>>>(out);
}

// round 17
// speedup vs baseline: 1.4056x; 1.0315x over previous
#include <cuda_runtime.h>
#include <cuda_bf16.h>
#include <cstdint>

#define B_    64
#define T_    512
#define F_    1024
#define H_    52
#define START_ 50
#define STOP_  51

__device__ float g_emitT[(size_t)B_ * H_ * T_]; // emit transposed [b][h][t]
__device__ float g_diff[B_];

// ---------- packed fp32x2 helpers (scan) ----------
__device__ __forceinline__ unsigned long long pk2(float lo, float hi) {
    unsigned long long d;
    asm("mov.b64 %0, {%1, %2};" : "=l"(d) : "r"(__float_as_uint(lo)), "r"(__float_as_uint(hi)));
    return d;
}
__device__ __forceinline__ void upk2(unsigned long long v, float& lo, float& hi) {
    unsigned int a, b;
    asm("mov.b64 {%0, %1}, %2;" : "=r"(a), "=r"(b) : "l"(v));
    lo = __uint_as_float(a); hi = __uint_as_float(b);
}
__device__ __forceinline__ unsigned long long fma2(unsigned long long a, unsigned long long b,
                                                   unsigned long long c) {
    unsigned long long d;
    asm("fma.rn.f32x2 %0, %1, %2, %3;" : "=l"(d) : "l"(a), "l"(b), "l"(c));
    return d;
}
__device__ __forceinline__ unsigned long long add2(unsigned long long a, unsigned long long b) {
    unsigned long long d;
    asm("add.rn.f32x2 %0, %1, %2;" : "=l"(d) : "l"(a), "l"(b));
    return d;
}
__device__ __forceinline__ uint32_t smem_u32(const void* p) {
    uint32_t a;
    asm("{ .reg .u64 t; cvta.to.shared.u64 t, %1; cvt.u32.u64 %0, t; }" : "=r"(a) : "l"(p));
    return a;
}

// ---------- tf32 mma (Ampere-class, valid on sm_103) ----------
__device__ __forceinline__ void mma_tf32(float* d, const uint32_t* a, uint32_t b0, uint32_t b1) {
    asm volatile(
        "mma.sync.aligned.m16n8k8.row.col.f32.tf32.tf32.f32 "
        "{%0,%1,%2,%3}, {%4,%5,%6,%7}, {%8,%9}, {%0,%1,%2,%3};"
        : "+f"(d[0]), "+f"(d[1]), "+f"(d[2]), "+f"(d[3])
        : "r"(a[0]), "r"(a[1]), "r"(a[2]), "r"(a[3]), "r"(b0), "r"(b1));
}

// ============================================================
// Kernel 1: emit = features @ W^T + b, tf32 mma + 3-stage cp.async.
// 128 blocks x 256 threads (SINGLE WAVE, 1 CTA/SM, no tail).
// 256-row tiles: warp w owns rows [32w,32w+32) = 2 m16 tiles x 7 n8
// (B-fragment reads amortized 2x vs 128-row tiles).
// Layout [row][k], stride 36 -> fragment LDS conflict-free.
// ============================================================
#define SRK 36
#define A_FL (256 * SRK)               // 9216 floats
#define B_FL (56 * SRK)                // 2016 floats
#define STAGE_FL (A_FL + B_FL)         // 11232 floats
#define NSTAGE 3
#define GEMM_SMEM_BYTES (NSTAGE * STAGE_FL * 4)   // 134784 B

__global__ void __launch_bounds__(256, 1)
emit_gemm_kernel(const float* __restrict__ feat, const float* __restrict__ W,
                 const float* __restrict__ bias) {
    extern __shared__ __align__(16) float smem[];
    const uint32_t su = smem_u32(smem);

    const int tid = threadIdx.x;
    const int lane = tid & 31;
    const int w = tid >> 5;            // warp 0..7
    const int a_ = lane >> 2;          // 0..7
    const int b_ = lane & 3;           // 0..3
    const int blockRow = blockIdx.x * 256;

    float c[2][7][4];
#pragma unroll
    for (int mt = 0; mt < 2; mt++)
#pragma unroll
        for (int nt = 0; nt < 7; nt++)
#pragma unroll
            for (int j = 0; j < 4; j++) c[mt][nt][j] = 0.0f;

    const int arow = tid >> 1;         // 0..127
    const int akq  = (tid & 1) * 4;    // quad base 0 or 4

    auto cp_stage = [&](int ch, int st) {
        const int k0 = ch * 32;
        const uint32_t sbase = su + (uint32_t)(st * STAGE_FL) * 4;
        // A: 256 rows x 8 quads = 2048 cp / 256 thr = 8 each (2 rows x 4 quads)
#pragma unroll
        for (int half = 0; half < 2; half++) {
            int row = arow + half * 128;
            const float* src = &feat[(size_t)(blockRow + row) * F_ + k0];
            uint32_t dst = sbase + (uint32_t)(row * SRK) * 4;
#pragma unroll
            for (int it = 0; it < 4; it++) {
                int kq = akq + it;
                asm volatile("cp.async.cg.shared.global [%0], [%1], 16;"
                             :: "r"(dst + (uint32_t)(kq * 4) * 4), "l"(src + kq * 4));
            }
        }
        // B: 52 rows x 8 quads = 416 cp; <=2 per thread
#pragma unroll
        for (int it = 0; it < 2; it++) {
            int idx = tid + it * 256;
            int n = idx >> 3;
            int kq = idx & 7;
            if (n < H_) {
                uint32_t dst = sbase + (uint32_t)(A_FL + n * SRK + kq * 4) * 4;
                const float* src = &W[(size_t)n * F_ + k0 + kq * 4];
                asm volatile("cp.async.cg.shared.global [%0], [%1], 16;"
                             :: "r"(dst), "l"(src));
            }
        }
        asm volatile("cp.async.commit_group;" ::: "memory");
    };

    auto compute = [&](int st) {
        const float* sA = smem + st * STAGE_FL;
        const float* sB = sA + A_FL;
        const int rb = w * 32;
#pragma unroll
        for (int ks = 0; ks < 4; ks++) {
            const int kb = ks * 8;
            uint32_t A0[4], A1[4];
            A0[0] = __float_as_uint(sA[(rb + a_) * SRK + kb + b_]);
            A0[1] = __float_as_uint(sA[(rb + a_ + 8) * SRK + kb + b_]);
            A0[2] = __float_as_uint(sA[(rb + a_) * SRK + kb + b_ + 4]);
            A0[3] = __float_as_uint(sA[(rb + a_ + 8) * SRK + kb + b_ + 4]);
            A1[0] = __float_as_uint(sA[(rb + 16 + a_) * SRK + kb + b_]);
            A1[1] = __float_as_uint(sA[(rb + 24 + a_) * SRK + kb + b_]);
            A1[2] = __float_as_uint(sA[(rb + 16 + a_) * SRK + kb + b_ + 4]);
            A1[3] = __float_as_uint(sA[(rb + 24 + a_) * SRK + kb + b_ + 4]);
#pragma unroll
            for (int nt = 0; nt < 7; nt++) {
                uint32_t B0 = __float_as_uint(sB[(nt * 8 + a_) * SRK + kb + b_]);
                uint32_t B1 = __float_as_uint(sB[(nt * 8 + a_) * SRK + kb + b_ + 4]);
                mma_tf32(c[0][nt], A0, B0, B1);
                mma_tf32(c[1][nt], A1, B0, B1);
            }
        }
    };

    // zero B pad rows (n 52..55) per stage
    for (int s = 0; s < NSTAGE; s++)
        for (int e = tid; e < 4 * SRK; e += 256)
            smem[s * STAGE_FL + A_FL + 52 * SRK + e] = 0.0f;
    __syncthreads();

    // prologue: chunks 0,1 in flight
    cp_stage(0, 0);
    cp_stage(1, 1);

#pragma unroll 1
    for (int ch = 0; ch < 32; ch++) {
        asm volatile("cp.async.wait_group 1;" ::: "memory");   // chunk ch landed
        __syncthreads();                                        // prev compute done; visible
        if (ch + 2 < 32) cp_stage(ch + 2, (ch + 2) % 3);
        else asm volatile("cp.async.commit_group;" ::: "memory");
        compute(ch % 3);
    }

    // ---- epilogue: stage [col][row], coalesced transposed store ----
    const int bIdx = blockRow >> 9;
    const int t0 = blockRow & 511;
    const size_t bbase = (size_t)bIdx * (H_ * T_);
    float* stage = smem;               // 28*258 = 7224 floats

    asm volatile("cp.async.wait_group 0;" ::: "memory");
    __syncthreads();
#pragma unroll 1
    for (int pass = 0; pass < 2; pass++) {
        const int cb = pass * 28;
#pragma unroll
        for (int mt = 0; mt < 2; mt++)
#pragma unroll
            for (int nt = 0; nt < 7; nt++)
#pragma unroll
                for (int j = 0; j < 4; j++) {
                    int col = nt * 8 + 2 * b_ + (j & 1);
                    int row = w * 32 + mt * 16 + a_ + ((j >> 1) * 8);
                    if (col >= cb && col < cb + 28)
                        stage[(col - cb) * 258 + row] = c[mt][nt][j];
                }
        __syncthreads();
        for (int e = tid; e < 28 * 256; e += 256) {
            int cc = e >> 8, r = e & 255;
            int colg = cb + cc;
            if (colg < H_)
                g_emitT[bbase + (size_t)colg * T_ + t0 + r] =
                    stage[cc * 258 + r] + __ldg(&bias[colg]);
        }
        __syncthreads();
    }
}

// ============================================================
// Kernel 2: CRF forward via BIDIRECTIONAL scan (frozen R13 config).
// ============================================================
__global__ void __launch_bounds__(64, 1)
crf_scan_kernel(const float* __restrict__ transition, const float* __restrict__ masks,
                const int* __restrict__ tags) {
    const int b = blockIdx.x;
    const int tid = threadIdx.x;
    const int w = tid >> 5;
    const int lane = tid & 31;
    const bool act = (lane < 26);
    const int d0 = 2 * lane;
    const int d1 = 2 * lane + 1;
    const int c0 = (d0 < H_) ? d0 : 0;
    const int c1 = (d1 < H_) ? d1 : 0;
    const int base = b * T_;
    const unsigned FULL = 0xFFFFFFFFu;

    __shared__ __align__(16) float bufs[2][2][128];
    __shared__ float fx[52], bx[52];
    __shared__ float offsm[2], goldsm[2], msumsm[2];

    const float* embB = &g_emitT[(size_t)b * (H_ * T_)];

    float gold = 0.0f, msum = 0.0f;
    for (int t = tid; t < T_; t += 64) {
        float mk = masks[base + t];
        int tg = tags[base + t];
        int pv = (t == 0) ? START_ : tags[base + t - 1];
        gold += mk * (embB[(size_t)tg * T_ + t] + transition[tg * H_ + pv]);
        msum += mk;
    }
#pragma unroll
    for (int s = 16; s > 0; s >>= 1) {
        gold += __shfl_xor_sync(FULL, gold, s);
        msum += __shfl_xor_sync(FULL, msum, s);
    }
    if (lane == 0) { goldsm[w] = gold; msumsm[w] = msum; }

    const float* e0 = embB + (size_t)c0 * T_;
    const float* e1 = embB + (size_t)c1 * T_;
    const float4* m4 = reinterpret_cast<const float4*>(&masks[base]);
    float (*myb)[128] = bufs[w];

    if (w == 0) {
        unsigned long long E2[52];
        {
            const float* r0 = &transition[c0 * H_];
            const float* r1 = &transition[c1 * H_];
#pragma unroll
            for (int s = 0; s < H_; s++) E2[s] = pk2(__expf(r0[s]), __expf(r1[s]));
        }
        float po0 = (d0 == START_) ? 1.0f : 0.0f;
        float po1 = 0.0f;
        *reinterpret_cast<float4*>(&myb[0][4 * lane]) = make_float4(po0, po0, po1, po1);
        float offset = 0.0f;

        float eC0[4], eC1[4];
        float4 rn0, rn1, rrn0, rrn1, mkC, mkN, mkN2;
        {
            float4 a = *reinterpret_cast<const float4*>(e0);
            float4 c = *reinterpret_cast<const float4*>(e1);
            eC0[0] = __expf(a.x); eC0[1] = __expf(a.y); eC0[2] = __expf(a.z); eC0[3] = __expf(a.w);
            eC1[0] = __expf(c.x); eC1[1] = __expf(c.y); eC1[2] = __expf(c.z); eC1[3] = __expf(c.w);
            rn0  = *reinterpret_cast<const float4*>(e0 + 4);
            rn1  = *reinterpret_cast<const float4*>(e1 + 4);
            rrn0 = *reinterpret_cast<const float4*>(e0 + 8);
            rrn1 = *reinterpret_cast<const float4*>(e1 + 8);
            mkC = m4[0]; mkN = m4[1]; mkN2 = m4[2];
        }
        __syncwarp();

        int cur = 0;
        for (int tb = 0; tb < 64; tb++) {
            float4 l0, l1, lm;
            const bool hv = (tb + 3 < 64);
            if (hv) {
                l0 = *reinterpret_cast<const float4*>(e0 + (tb + 3) * 4);
                l1 = *reinterpret_cast<const float4*>(e1 + (tb + 3) * 4);
                lm = m4[tb + 3];
            }
            float eN0[4], eN1[4];
            eN0[0] = __expf(rn0.x); eN0[1] = __expf(rn0.y); eN0[2] = __expf(rn0.z); eN0[3] = __expf(rn0.w);
            eN1[0] = __expf(rn1.x); eN1[1] = __expf(rn1.y); eN1[2] = __expf(rn1.z); eN1[3] = __expf(rn1.w);

            float rinv = 1.0f;
            if (tb) {
                float r = __shfl_sync(FULL, po0, 0);
                rinv = 1.0f / r;
                offset += __logf(r);
            }
            float mk[4] = {mkC.x, mkC.y, mkC.z, mkC.w};

#pragma unroll
            for (int s = 0; s < 4; s++) {
                const ulonglong2* u = reinterpret_cast<const ulonglong2*>(&myb[cur][0]);
                unsigned long long A0 = 0ULL, A1 = 0ULL, A2 = 0ULL, A3 = 0ULL;
#pragma unroll
                for (int q = 0; q < 26; q++) {
                    ulonglong2 uq = u[q];
                    if (q & 1) { A2 = fma2(E2[2 * q], uq.x, A2); A3 = fma2(E2[2 * q + 1], uq.y, A3); }
                    else       { A0 = fma2(E2[2 * q], uq.x, A0); A1 = fma2(E2[2 * q + 1], uq.y, A1); }
                }
                unsigned long long S2 = add2(add2(A0, A1), add2(A2, A3));
                float S0, S1;
                upk2(S2, S0, S1);
                bool on = (mk[s] > 0.5f);
                float n0 = on ? S0 * eC0[s] : po0;
                float n1 = on ? S1 * eC1[s] : po1;
                if (s == 0) { n0 *= rinv; n1 *= rinv; }
                *reinterpret_cast<float4*>(&myb[cur ^ 1][4 * lane]) = make_float4(n0, n0, n1, n1);
                po0 = n0; po1 = n1;
                cur ^= 1;
                __syncwarp();
            }

            eC0[0] = eN0[0]; eC0[1] = eN0[1]; eC0[2] = eN0[2]; eC0[3] = eN0[3];
            eC1[0] = eN1[0]; eC1[1] = eN1[1]; eC1[2] = eN1[2]; eC1[3] = eN1[3];
            rn0 = rrn0; rn1 = rrn1;
            mkC = mkN; mkN = mkN2;
            if (hv) { rrn0 = l0; rrn1 = l1; mkN2 = lm; }
        }
        if (act) { fx[d0] = po0; fx[d1] = po1; }
        if (lane == 0) offsm[0] = offset;
    } else {
        unsigned long long E2[52];
        {
#pragma unroll
            for (int dd = 0; dd < H_; dd++)
                E2[dd] = pk2(__expf(transition[dd * H_ + c0]), __expf(transition[dd * H_ + c1]));
        }
        float ro0 = __expf(transition[STOP_ * H_ + c0]);
        float ro1 = __expf(transition[STOP_ * H_ + c1]);
        float offset = 0.0f;

        float eC0[4], eC1[4];
        float4 rn0, rn1, rrn0, rrn1, mkC, mkN, mkN2;
        {
            float4 a = *reinterpret_cast<const float4*>(e0 + 127 * 4);
            float4 c = *reinterpret_cast<const float4*>(e1 + 127 * 4);
            eC0[0] = __expf(a.x); eC0[1] = __expf(a.y); eC0[2] = __expf(a.z); eC0[3] = __expf(a.w);
            eC1[0] = __expf(c.x); eC1[1] = __expf(c.y); eC1[2] = __expf(c.z); eC1[3] = __expf(c.w);
            rn0  = *reinterpret_cast<const float4*>(e0 + 126 * 4);
            rn1  = *reinterpret_cast<const float4*>(e1 + 126 * 4);
            rrn0 = *reinterpret_cast<const float4*>(e0 + 125 * 4);
            rrn1 = *reinterpret_cast<const float4*>(e1 + 125 * 4);
            mkC = m4[127]; mkN = m4[126]; mkN2 = m4[125];
        }
        __syncwarp();

        int cur = 0;
        for (int tb = 127; tb >= 64; tb--) {
            float4 l0, l1, lm;
            const bool hv = (tb - 3 >= 64);
            if (hv) {
                l0 = *reinterpret_cast<const float4*>(e0 + (tb - 3) * 4);
                l1 = *reinterpret_cast<const float4*>(e1 + (tb - 3) * 4);
                lm = m4[tb - 3];
            }
            float eN0[4], eN1[4];
            eN0[0] = __expf(rn0.x); eN0[1] = __expf(rn0.y); eN0[2] = __expf(rn0.z); eN0[3] = __expf(rn0.w);
            eN1[0] = __expf(rn1.x); eN1[1] = __expf(rn1.y); eN1[2] = __expf(rn1.z); eN1[3] = __expf(rn1.w);

            float rinv = 1.0f;
            if (tb != 127) {
                float r = __shfl_sync(FULL, ro0, 0);
                rinv = 1.0f / r;
                offset += __logf(r);
            }
            float mk[4] = {mkC.x, mkC.y, mkC.z, mkC.w};

#pragma unroll
            for (int si = 0; si < 4; si++) {
                const int s = 3 - si;
                float w0 = eC0[s] * ro0;
                float w1 = eC1[s] * ro1;
                *reinterpret_cast<float4*>(&myb[cur][4 * lane]) = make_float4(w0, w0, w1, w1);
                __syncwarp();
                const ulonglong2* u = reinterpret_cast<const ulonglong2*>(&myb[cur][0]);
                unsigned long long A0 = 0ULL, A1 = 0ULL, A2 = 0ULL, A3 = 0ULL;
#pragma unroll
                for (int q = 0; q < 26; q++) {
                    ulonglong2 uq = u[q];
                    if (q & 1) { A2 = fma2(E2[2 * q], uq.x, A2); A3 = fma2(E2[2 * q + 1], uq.y, A3); }
                    else       { A0 = fma2(E2[2 * q], uq.x, A0); A1 = fma2(E2[2 * q + 1], uq.y, A1); }
                }
                unsigned long long S2 = add2(add2(A0, A1), add2(A2, A3));
                float S0, S1;
                upk2(S2, S0, S1);
                bool on = (mk[s] > 0.5f);
                float n0 = on ? S0 : ro0;
                float n1 = on ? S1 : ro1;
                if (s == 3) { n0 *= rinv; n1 *= rinv; }
                ro0 = n0; ro1 = n1;
                cur ^= 1;
            }

            eC0[0] = eN0[0]; eC0[1] = eN0[1]; eC0[2] = eN0[2]; eC0[3] = eN0[3];
            eC1[0] = eN1[0]; eC1[1] = eN1[1]; eC1[2] = eN1[2]; eC1[3] = eN1[3];
            rn0 = rrn0; rn1 = rrn1;
            mkC = mkN; mkN = mkN2;
            if (hv) { rrn0 = l0; rrn1 = l1; mkN2 = lm; }
        }
        if (act) { bx[d0] = ro0; bx[d1] = ro1; }
        if (lane == 0) offsm[1] = offset;
    }

    __syncthreads();
    if (w == 0) {
        float term = act ? (fx[d0] * bx[d0] + fx[d1] * bx[d1]) : 0.0f;
#pragma unroll
        for (int s = 16; s > 0; s >>= 1) term += __shfl_xor_sync(FULL, term, s);
        if (lane == 0) {
            float goldT = goldsm[0] + goldsm[1];
            float msumT = msumsm[0] + msumsm[1];
            int lp = (int)(msumT + 0.5f);
            int lt = (lp > 0) ? tags[base + lp - 1] : START_;
            goldT += transition[STOP_ * H_ + lt];
            g_diff[b] = offsm[0] + offsm[1] + __logf(term) - goldT;
        }
    }
}

// ============================================================
// Kernel 3: mean over batches
// ============================================================
__global__ void __launch_bounds__(64)
finalize_kernel(float* __restrict__ out) {
    __shared__ float red[64];
    int tid = threadIdx.x;
    red[tid] = g_diff[tid];
    __syncthreads();
    for (int s = 32; s > 0; s >>= 1) { if (tid < s) red[tid] += red[tid + s]; __syncthreads(); }
    if (tid == 0) out[0] = red[0] * (1.0f / (float)B_);
}

// ============================================================
// launch
// ============================================================
extern "C" void kernel_launch(void* const* d_in, const int* in_sizes, int n_in,
                              void* d_out, int out_size) {
    const float* feat  = (const float*)d_in[0];
    const float* W     = (const float*)d_in[1];
    const float* bias  = (const float*)d_in[2];
    const float* trans = (const float*)d_in[3];
    const float* masks = (const float*)d_in[4];
    const int*   tags  = (const int*)d_in[5];
    float* out = (float*)d_out;

    cudaFuncSetAttribute(emit_gemm_kernel,
                         cudaFuncAttributeMaxDynamicSharedMemorySize, GEMM_SMEM_BYTES);

    emit_gemm_kernel<<<128, 256, GEMM_SMEM_BYTES>>>(feat, W, bias);
    crf_scan_kernel<<<B_, 64>>>(trans, masks, tags);
    finalize_kernel<<<1, 64>>>(out);
}